// round 3
// baseline (speedup 1.0000x reference)
#include <cuda_runtime.h>
#include <cstdint>

#define NN    7680
#define NASM  256
#define CAPA  30
#define BATCH 64
#define KMAX  8
#define NT    256
#define RPT   30     // NN / NT
#define MAXC  960    // >= 30 assemblies * 30 cols hard bound on positive candidates

__device__ float g_invc[NN];

static __device__ __forceinline__ unsigned long long make_key(float v, int j){
    // v > 0 guaranteed. Bigger value -> bigger key; equal value -> smaller j wins.
    return (((unsigned long long)__float_as_uint(v)) << 32) | (unsigned int)(NN - 1 - j);
}
static __device__ __forceinline__ int key_j(unsigned long long k){
    return NN - 1 - (int)(k & 0xffffffffull);
}

// ---------------------------------------------------------------------------
// colnorm: inv_c[j] = 1 / max(sum_i W_rec[i][j] * (p[i/30]==j/30), 1e-6)
// Integer counts -> exact in fp32 regardless of order.
// ---------------------------------------------------------------------------
__global__ void colnorm_kernel(const int* __restrict__ p, const float* __restrict__ W_rec){
    __shared__ int sp[NASM];
    int tid = threadIdx.x;
    sp[tid] = p[tid];
    __syncthreads();
    int j  = blockIdx.x * NT + tid;
    int aj = j / CAPA;
    float c = 0.f;
    for (int q = 0; q < NASM; ++q){
        if (sp[q] == aj){
            const float* base = W_rec + (size_t)q * CAPA * NN + j;
            #pragma unroll
            for (int m = 0; m < CAPA; ++m) c += base[(size_t)m * NN];
        }
    }
    g_invc[j] = 1.0f / fmaxf(c, 1e-6f);
}

// ---------------------------------------------------------------------------
// Main: one block per batch sample does the whole pipeline.
// ---------------------------------------------------------------------------
__global__ void __launch_bounds__(NT) pointer_ac_kernel(
    const int* __restrict__ p, const int* __restrict__ s, const int* __restrict__ k,
    const float* __restrict__ W_in, const float* __restrict__ W_rec,
    float* __restrict__ out)
{
    __shared__ float sc[NN];
    __shared__ unsigned long long cand[MAXC];
    __shared__ int sp[NASM];
    __shared__ int scnt[NASM];
    __shared__ unsigned char sflag[NASM];
    __shared__ int act[CAPA];
    __shared__ int stgt[CAPA];
    __shared__ int sel[CAPA];
    __shared__ unsigned long long swred[8];
    __shared__ unsigned long long sbest;
    __shared__ int sncand;
    __shared__ int snsel;
    __shared__ int sbesta;

    const int b    = blockIdx.x;
    const int tid  = threadIdx.x;
    const int lane = tid & 31;
    const int wid  = tid >> 5;

    sp[tid] = p[tid];
    const int kb = k[b];
    const int sb = s[b];
    __syncthreads();

    // ================= Step 1: scores = sum of 30 contiguous W_in rows ======
    {
        const float* Wrow = W_in + (size_t)sb * CAPA * NN;
        #pragma unroll 1
        for (int r = 0; r < 15; ++r){
            int pj = tid + (r << 8);            // float2 pair index 0..3839
            float ax = 0.f, ay = 0.f;
            #pragma unroll
            for (int m = 0; m < CAPA; ++m){
                float2 w = *(const float2*)(Wrow + (size_t)m * NN + 2 * pj);
                ax += w.x; ay += w.y;
            }
            sc[2 * pj]     = ax;
            sc[2 * pj + 1] = ay;
        }
    }
    __syncthreads();

    // ================= dense kWTA (top-30, value desc / index asc) ==========
    {
        unsigned long long mymax = 0ull;
        #pragma unroll
        for (int r = 0; r < RPT; ++r){
            int j = tid + (r << 8);
            float v = sc[j];
            if (v > 0.f){ unsigned long long kk = make_key(v, j); if (kk > mymax) mymax = kk; }
        }
        if (tid == 0) snsel = 0;
        __syncthreads();

        for (int it = 0; it < CAPA; ++it){
            unsigned long long m = mymax;
            #pragma unroll
            for (int o = 16; o > 0; o >>= 1){
                unsigned long long other = __shfl_down_sync(0xffffffffu, m, o);
                if (other > m) m = other;
            }
            if (lane == 0) swred[wid] = m;
            __syncthreads();
            if (tid == 0){
                unsigned long long bb = swred[0];
                #pragma unroll
                for (int w = 1; w < 8; ++w) if (swred[w] > bb) bb = swred[w];
                sbest = bb;
                if (bb) sel[snsel++] = key_j(bb);
            }
            __syncthreads();
            unsigned long long best = sbest;
            if (!best) break;                   // uniform across block
            if (mymax == best){                 // unique owner removes + rescans
                sc[key_j(best)] = -1.f;
                mymax = 0ull;
                #pragma unroll
                for (int r = 0; r < RPT; ++r){
                    int j = tid + (r << 8);
                    float v = sc[j];
                    if (v > 0.f){ unsigned long long kk = make_key(v, j); if (kk > mymax) mymax = kk; }
                }
            }
        }
        __syncthreads();
        if (tid == 0){                          // zero-fill with smallest-index zeros
            int P = snsel;
            int j = 0;
            while (P < CAPA){ if (sc[j] == 0.0f) sel[P++] = j; ++j; }
        }
        __syncthreads();
        if (tid < CAPA) act[tid] = sel[tid];
        __syncthreads();
    }

    // ================= recurrent pointer-chase steps ========================
    for (int t = 0; t < KMAX; ++t){
        if (t >= kb) break;                     // per-sample freeze (uniform per block)

        sflag[tid] = 0;
        if (tid == 0) sncand = 0;
        __syncthreads();
        if (tid < CAPA){
            int tg = sp[act[tid] / CAPA];
            stgt[tid] = tg;
            sflag[tg] = 1;                      // benign same-value races
        }
        __syncthreads();

        // scores: only candidate columns (target assemblies) touch memory
        #pragma unroll 1
        for (int r = 0; r < RPT; ++r){
            int j  = tid + (r << 8);
            int aj = j / CAPA;
            float vv = 0.f;
            if (sflag[aj]){
                float ic = g_invc[j];
                const float* col = W_rec + j;
                #pragma unroll
                for (int m = 0; m < CAPA; ++m){
                    if (stgt[m] == aj){
                        float w = __ldg(col + (size_t)act[m] * NN);
                        vv += w * ic;           // w in {0,1}: exact sequential adds of ic
                    }
                }
            }
            sc[j] = vv;
            if (vv > 0.f){
                int slot = atomicAdd(&sncand, 1);
                if (slot < MAXC) cand[slot] = make_key(vv, j);
            }
        }
        __syncthreads();

        int nc = sncand; if (nc > MAXC) nc = MAXC;
        // warp-0 rank-select among positive candidates (strict total order via keys)
        if (tid < 32){
            for (int q = tid; q < nc; q += 32){
                unsigned long long kq = cand[q];
                int rank = 0;
                for (int x = 0; x < nc; ++x) rank += (cand[x] > kq);
                if (rank < CAPA) sel[rank] = key_j(kq);
            }
        }
        __syncthreads();
        if (tid == 0 && nc < CAPA){
            int P = nc;
            int j = 0;
            while (P < CAPA){ if (sc[j] == 0.0f) sel[P++] = j; ++j; }
        }
        __syncthreads();
        if (tid < CAPA) act[tid] = sel[tid];
        __syncthreads();
    }

    // ================= overlaps -> argmax -> one-hot ========================
    scnt[tid] = 0;
    __syncthreads();
    if (tid < CAPA) atomicAdd(&scnt[act[tid] / CAPA], 1);
    __syncthreads();
    if (tid == 0){
        int bi = 0, bc = scnt[0];
        for (int a = 1; a < NASM; ++a){ if (scnt[a] > bc){ bc = scnt[a]; bi = a; } }
        sbesta = bi;
    }
    __syncthreads();
    out[(size_t)b * NASM + tid] = (tid == sbesta) ? 1.0f : 0.0f;
}

// ---------------------------------------------------------------------------
extern "C" void kernel_launch(void* const* d_in, const int* in_sizes, int n_in,
                              void* d_out, int out_size)
{
    const int*   p     = (const int*)d_in[0];     // [256]
    const int*   s     = (const int*)d_in[1];     // [64]
    const int*   k     = (const int*)d_in[2];     // [64]
    const float* W_in  = (const float*)d_in[3];   // [7680*7680]
    const float* W_rec = (const float*)d_in[4];   // [7680*7680]
    float*       out   = (float*)d_out;           // [64*256]

    colnorm_kernel<<<NN / NT, NT>>>(p, W_rec);
    pointer_ac_kernel<<<BATCH, NT>>>(p, s, k, W_in, W_rec, out);
}

// round 4
// speedup vs baseline: 1.8099x; 1.8099x over previous
#include <cuda_runtime.h>
#include <cstdint>

#define NN     7680
#define NASM   256
#define CAPA   30
#define BATCH  64
#define KMAX   8
#define NTC    256     // colnorm block
#define NTM    512     // main block
#define RPTM   15      // NN / NTM
#define NSPLIT 15      // step1 column chunks (512 cols / 128 float4 each)
#define MAXC   960

__device__ float g_invc[NN];
__device__ float g_scores[BATCH][NN];

static __device__ __forceinline__ unsigned long long make_key(float v, int j){
    // v > 0. Bigger value -> bigger key; equal value -> smaller j wins.
    return (((unsigned long long)__float_as_uint(v)) << 32) | (unsigned int)(NN - 1 - j);
}
static __device__ __forceinline__ int key_j(unsigned long long k){
    return NN - 1 - (int)(k & 0xffffffffull);
}

// ---------------------------------------------------------------------------
// colnorm: inv_c[j] = 1 / max(sum_i W_rec[i][j] * (p[i/30]==j/30), 1e-6)
// ---------------------------------------------------------------------------
__global__ void colnorm_kernel(const int* __restrict__ p, const float* __restrict__ W_rec){
    __shared__ int sp[NASM];
    int tid = threadIdx.x;
    sp[tid] = p[tid];
    __syncthreads();
    int j  = blockIdx.x * NTC + tid;
    int aj = j / CAPA;
    float c = 0.f;
    for (int q = 0; q < NASM; ++q){
        if (sp[q] == aj){
            const float* base = W_rec + (size_t)q * CAPA * NN + j;
            #pragma unroll
            for (int m = 0; m < CAPA; ++m) c += base[(size_t)m * NN];
        }
    }
    g_invc[j] = 1.0f / fmaxf(c, 1e-6f);
}

// ---------------------------------------------------------------------------
// step1: g_scores[b][j] = sum of 30 contiguous W_in rows (assembly s[b]).
// grid (NSPLIT, BATCH) x 128 threads; float4 lanes. Integer counts -> exact.
// ---------------------------------------------------------------------------
__global__ void __launch_bounds__(128) step1_kernel(
    const int* __restrict__ s, const float* __restrict__ W_in)
{
    const int b  = blockIdx.y;
    const int c4 = blockIdx.x * 128 + threadIdx.x;    // float4 index 0..1919
    const float4* src = (const float4*)(W_in + (size_t)__ldg(&s[b]) * CAPA * NN) + c4;
    float ax = 0.f, ay = 0.f, az = 0.f, aw = 0.f;
    #pragma unroll
    for (int m = 0; m < CAPA; ++m){
        float4 w = __ldg(src + (size_t)m * (NN / 4));
        ax += w.x; ay += w.y; az += w.z; aw += w.w;
    }
    float4 r; r.x = ax; r.y = ay; r.z = az; r.w = aw;
    ((float4*)g_scores[b])[c4] = r;
}

// ---------------------------------------------------------------------------
// Main: one block per sample. Histogram kWTA + sparse pointer-chase.
// ---------------------------------------------------------------------------
__global__ void __launch_bounds__(NTM) pointer_ac_kernel(
    const int* __restrict__ p, const int* __restrict__ k,
    const float* __restrict__ W_rec, float* __restrict__ out)
{
    __shared__ float sc[NN];
    __shared__ unsigned long long cand[MAXC];
    __shared__ int   warpHist[16 * 31];
    __shared__ int   hist[31];
    __shared__ int   sp[NASM];
    __shared__ int   scnt[NASM];
    __shared__ unsigned char sflag[NASM];
    __shared__ int   act[CAPA];
    __shared__ int   stgt[CAPA];
    __shared__ int   sel[CAPA];
    __shared__ int   warpSum[16], warpOff[16];
    __shared__ int   sT, sNG, sticket, sncand, sbesta;

    const int b    = blockIdx.x;
    const int tid  = threadIdx.x;
    const int lane = tid & 31;
    const int wid  = tid >> 5;

    if (tid < NASM) sp[tid] = p[tid];
    const int kb = __ldg(&k[b]);
    if (tid < 16 * 31) warpHist[tid] = 0;
    if (tid == 0){ sticket = 0; }

    // load scores (coalesced)
    #pragma unroll
    for (int r = 0; r < RPTM; ++r){
        int j = tid + r * NTM;
        sc[j] = g_scores[b][j];
    }
    __syncthreads();

    // ====== dense kWTA via histogram (values are exact ints 0..30) ==========
    {
        int* myh = warpHist + wid * 31;
        const int base_j = tid * RPTM;                 // contiguous segment per thread
        #pragma unroll
        for (int i = 0; i < RPTM; ++i){
            int v = (int)sc[base_j + i];
            atomicAdd(&myh[v], 1);
        }
        __syncthreads();
        if (tid < 31){
            int c = 0;
            #pragma unroll
            for (int w = 0; w < 16; ++w) c += warpHist[w * 31 + tid];
            hist[tid] = c;
        }
        __syncthreads();
        if (tid == 0){
            int suf = 0, T = 0, ng = 0;
            for (int v = 30; v >= 0; --v){
                suf += hist[v];
                if (suf >= CAPA){ T = v; ng = suf - hist[v]; break; }
            }
            sT = T; sNG = ng;
        }
        __syncthreads();
        const int T  = sT;
        const int ng = sNG;
        const int need = CAPA - ng;

        // exclusive prefix of (==T) counts over contiguous thread segments
        int cntT = 0;
        #pragma unroll
        for (int i = 0; i < RPTM; ++i) cntT += ((int)sc[base_j + i] == T);
        int incl = cntT;
        #pragma unroll
        for (int o = 1; o < 32; o <<= 1){
            int n = __shfl_up_sync(0xffffffffu, incl, o);
            if (lane >= o) incl += n;
        }
        if (lane == 31) warpSum[wid] = incl;
        __syncthreads();
        if (tid == 0){
            int run = 0;
            #pragma unroll
            for (int w = 0; w < 16; ++w){ warpOff[w] = run; run += warpSum[w]; }
        }
        __syncthreads();
        int slotT = warpOff[wid] + incl - cntT;

        #pragma unroll
        for (int i = 0; i < RPTM; ++i){
            int j = base_j + i;
            int v = (int)sc[j];
            if (v > T){
                int sl = atomicAdd(&sticket, 1);       // 0..ng-1, set order irrelevant
                sel[sl] = j;
            } else if (v == T){
                if (slotT < need) sel[ng + slotT] = j; // smallest-index ties
                ++slotT;
            }
        }
        __syncthreads();
        if (tid < CAPA) act[tid] = sel[tid];
        __syncthreads();
    }

    // ====== recurrent pointer-chase steps ===================================
    for (int t = 0; t < KMAX; ++t){
        if (t >= kb) break;                            // uniform per block

        if (tid < NASM) sflag[tid] = 0;
        if (tid == 0) sncand = 0;
        __syncthreads();
        if (tid < CAPA){
            int tg = sp[act[tid] / CAPA];
            stgt[tid] = tg;
            sflag[tg] = 1;
        }
        __syncthreads();

        #pragma unroll 1
        for (int r = 0; r < RPTM; ++r){
            int j  = tid + r * NTM;
            int aj = j / CAPA;
            float vv = 0.f;
            if (sflag[aj]){
                float ic = g_invc[j];
                const float* col = W_rec + j;
                #pragma unroll
                for (int m = 0; m < CAPA; ++m){
                    if (stgt[m] == aj){
                        float w = __ldg(col + (size_t)act[m] * NN);
                        vv += w * ic;
                    }
                }
            }
            sc[j] = vv;
            if (vv > 0.f){
                int slot = atomicAdd(&sncand, 1);
                if (slot < MAXC) cand[slot] = make_key(vv, j);
            }
        }
        __syncthreads();

        int nc = sncand; if (nc > MAXC) nc = MAXC;
        // all-thread rank-select among positive candidates
        for (int q = tid; q < nc; q += NTM){
            unsigned long long kq = cand[q];
            int rank = 0;
            for (int x = 0; x < nc; ++x) rank += (cand[x] > kq);
            if (rank < CAPA) sel[rank] = key_j(kq);
        }
        __syncthreads();
        if (tid == 0 && nc < CAPA){
            int P = nc, j = 0;
            while (P < CAPA){ if (sc[j] == 0.0f) sel[P++] = j; ++j; }
        }
        __syncthreads();
        if (tid < CAPA) act[tid] = sel[tid];
        __syncthreads();
    }

    // ====== overlaps -> argmax -> one-hot ===================================
    if (tid < NASM) scnt[tid] = 0;
    __syncthreads();
    if (tid < CAPA) atomicAdd(&scnt[act[tid] / CAPA], 1);
    __syncthreads();
    if (tid == 0){
        int bi = 0, bc = scnt[0];
        for (int a = 1; a < NASM; ++a){ if (scnt[a] > bc){ bc = scnt[a]; bi = a; } }
        sbesta = bi;
    }
    __syncthreads();
    if (tid < NASM) out[(size_t)b * NASM + tid] = (tid == sbesta) ? 1.0f : 0.0f;
}

// ---------------------------------------------------------------------------
extern "C" void kernel_launch(void* const* d_in, const int* in_sizes, int n_in,
                              void* d_out, int out_size)
{
    const int*   p     = (const int*)d_in[0];     // [256]
    const int*   s     = (const int*)d_in[1];     // [64]
    const int*   k     = (const int*)d_in[2];     // [64]
    const float* W_in  = (const float*)d_in[3];   // [7680*7680]
    const float* W_rec = (const float*)d_in[4];   // [7680*7680]
    float*       out   = (float*)d_out;           // [64*256]

    colnorm_kernel<<<NN / NTC, NTC>>>(p, W_rec);
    dim3 g1(NSPLIT, BATCH);
    step1_kernel<<<g1, 128>>>(s, W_in);
    pointer_ac_kernel<<<BATCH, NTM>>>(p, k, W_rec, out);
}

// round 5
// speedup vs baseline: 1.8404x; 1.0168x over previous
#include <cuda_runtime.h>
#include <cstdint>

#define NN     7680
#define NASM   256
#define CAPA   30
#define BATCH  64
#define KMAX   8
#define NTM    512
#define RPTM   15      // NN / NTM
#define MAXC   960
#define S1BLK  960     // step1 blocks: 15 chunks x 64 samples (128 thr x float4)

__device__ float g_invc[NN];
__device__ float g_scores[BATCH][NN];

static __device__ __forceinline__ unsigned long long make_key(float v, int j){
    // v > 0. Bigger value -> bigger key; equal value -> smaller j wins.
    return (((unsigned long long)__float_as_uint(v)) << 32) | (unsigned int)(NN - 1 - j);
}
static __device__ __forceinline__ int key_j(unsigned long long k){
    return NN - 1 - (int)(k & 0xffffffffull);
}

// ---------------------------------------------------------------------------
// Fused prep: blocks [0,960) do step1 (scores), blocks [960,1216) do colnorm.
// Both produce exact integer counts -> fp32-exact in any order.
// ---------------------------------------------------------------------------
__global__ void __launch_bounds__(128) prep_kernel(
    const int* __restrict__ p, const int* __restrict__ s,
    const float* __restrict__ W_in, const float* __restrict__ W_rec)
{
    const int bid = blockIdx.x;
    const int tid = threadIdx.x;
    if (bid < S1BLK){
        // ---- step1: g_scores[b][:] = sum of 30 contiguous W_in rows -------
        const int b  = bid / 15;
        const int c4 = (bid % 15) * 128 + tid;        // float4 index 0..1919
        const float4* src = (const float4*)(W_in + (size_t)__ldg(&s[b]) * CAPA * NN) + c4;
        float ax = 0.f, ay = 0.f, az = 0.f, aw = 0.f;
        #pragma unroll
        for (int m = 0; m < CAPA; ++m){
            float4 w = __ldg(src + (size_t)m * (NN / 4));
            ax += w.x; ay += w.y; az += w.z; aw += w.w;
        }
        float4 r; r.x = ax; r.y = ay; r.z = az; r.w = aw;
        ((float4*)g_scores[b])[c4] = r;
    } else {
        // ---- colnorm for destination assembly a ---------------------------
        __shared__ int   sp[NASM];
        __shared__ float acc[CAPA];
        const int a = bid - S1BLK;                    // 0..255
        sp[tid]       = p[tid];
        sp[tid + 128] = p[tid + 128];
        if (tid < CAPA) acc[tid] = 0.f;
        __syncthreads();
        for (int q = 0; q < NASM; ++q){
            if (sp[q] == a){
                const float* base = W_rec + (size_t)q * CAPA * NN + a * CAPA;
                for (int i = tid; i < CAPA * CAPA; i += 128){
                    int m = i / CAPA, c = i % CAPA;
                    atomicAdd(&acc[c], __ldg(base + (size_t)m * NN + c));
                }
            }
        }
        __syncthreads();
        if (tid < CAPA) g_invc[a * CAPA + tid] = 1.0f / fmaxf(acc[tid], 1e-6f);
    }
}

// ---------------------------------------------------------------------------
// Main: one block per sample. Histogram kWTA + direct-candidate pointer-chase.
// ---------------------------------------------------------------------------
__global__ void __launch_bounds__(NTM) pointer_ac_kernel(
    const int* __restrict__ p, const int* __restrict__ k,
    const float* __restrict__ W_rec, float* __restrict__ out)
{
    __shared__ float sc[NN];
    __shared__ unsigned long long cand[MAXC];
    __shared__ unsigned int bmap[NN / 32];            // positive-candidate bitmap
    __shared__ int   warpHist[16 * 31];
    __shared__ int   hist[31];
    __shared__ int   sp[NASM];
    __shared__ int   scnt[NASM];
    __shared__ unsigned char sflag[NASM];
    __shared__ int   act[CAPA];
    __shared__ int   stgt[CAPA];
    __shared__ int   sel[CAPA];
    __shared__ int   tgtl[CAPA];
    __shared__ int   warpSum[16], warpOff[16];
    __shared__ int   sT, sNG, sticket, sncand, sntgt, sbesta;

    const int b    = blockIdx.x;
    const int tid  = threadIdx.x;
    const int lane = tid & 31;
    const int wid  = tid >> 5;

    if (tid < NASM) sp[tid] = p[tid];
    const int kb = __ldg(&k[b]);
    if (tid < 16 * 31) warpHist[tid] = 0;
    if (tid == 0) sticket = 0;

    #pragma unroll
    for (int r = 0; r < RPTM; ++r){
        int j = tid + r * NTM;
        sc[j] = g_scores[b][j];
    }
    __syncthreads();

    // ====== dense kWTA via histogram (values are exact ints 0..30) ==========
    {
        int* myh = warpHist + wid * 31;
        const int base_j = tid * RPTM;                // contiguous segment per thread
        #pragma unroll
        for (int i = 0; i < RPTM; ++i){
            int v = (int)sc[base_j + i];
            atomicAdd(&myh[v], 1);
        }
        __syncthreads();
        if (tid < 31){
            int c = 0;
            #pragma unroll
            for (int w = 0; w < 16; ++w) c += warpHist[w * 31 + tid];
            hist[tid] = c;
        }
        __syncthreads();
        if (tid == 0){
            int suf = 0, T = 0, ng = 0;
            for (int v = 30; v >= 0; --v){
                suf += hist[v];
                if (suf >= CAPA){ T = v; ng = suf - hist[v]; break; }
            }
            sT = T; sNG = ng;
        }
        __syncthreads();
        const int T    = sT;
        const int ng   = sNG;
        const int need = CAPA - ng;

        int cntT = 0;
        #pragma unroll
        for (int i = 0; i < RPTM; ++i) cntT += ((int)sc[base_j + i] == T);
        int incl = cntT;
        #pragma unroll
        for (int o = 1; o < 32; o <<= 1){
            int n = __shfl_up_sync(0xffffffffu, incl, o);
            if (lane >= o) incl += n;
        }
        if (lane == 31) warpSum[wid] = incl;
        __syncthreads();
        if (tid == 0){
            int run = 0;
            #pragma unroll
            for (int w = 0; w < 16; ++w){ warpOff[w] = run; run += warpSum[w]; }
        }
        __syncthreads();
        int slotT = warpOff[wid] + incl - cntT;

        #pragma unroll
        for (int i = 0; i < RPTM; ++i){
            int j = base_j + i;
            int v = (int)sc[j];
            if (v > T){
                int sl = atomicAdd(&sticket, 1);      // set order irrelevant
                sel[sl] = j;
            } else if (v == T){
                if (slotT < need) sel[ng + slotT] = j;
                ++slotT;
            }
        }
        __syncthreads();
        if (tid < CAPA) act[tid] = sel[tid];
        __syncthreads();
    }

    // ====== recurrent pointer-chase steps (direct candidate enumeration) ===
    for (int t = 0; t < KMAX; ++t){
        if (t >= kb) break;                           // uniform per block

        if (tid < NASM) sflag[tid] = 0;
        if (tid < NN / 32) bmap[tid] = 0;
        if (tid == 0){ sncand = 0; sntgt = 0; }
        __syncthreads();
        if (tid < CAPA){
            int tg = sp[act[tid] / CAPA];
            stgt[tid] = tg;
            sflag[tg] = 1;
        }
        __syncthreads();
        if (tid < NASM && sflag[tid]){
            int pos = atomicAdd(&sntgt, 1);
            tgtl[pos] = tid;
        }
        __syncthreads();

        const int items = sntgt * CAPA;               // <= 900
        for (int i = tid; i < items; i += NTM){
            int a  = tgtl[i / CAPA];
            int j  = a * CAPA + i % CAPA;
            float ic = g_invc[j];
            float vv = 0.f;
            const float* col = W_rec + j;
            #pragma unroll
            for (int m = 0; m < CAPA; ++m){
                if (stgt[m] == a){
                    float w = __ldg(col + (size_t)act[m] * NN);
                    vv += w * ic;                     // w in {0,1}: adds of ic, m ascending
                }
            }
            if (vv > 0.f){
                int slot = atomicAdd(&sncand, 1);
                cand[slot] = make_key(vv, j);
                atomicOr(&bmap[j >> 5], 1u << (j & 31));
            }
        }
        __syncthreads();

        const int nc = sncand;
        for (int q = tid; q < nc; q += NTM){
            unsigned long long kq = cand[q];
            int rank = 0;
            for (int x = 0; x < nc; ++x) rank += (cand[x] > kq);
            if (rank < CAPA) sel[rank] = key_j(kq);
        }
        __syncthreads();
        if (tid == 0 && nc < CAPA){
            int P = nc, j = 0;
            while (P < CAPA){
                if (!((bmap[j >> 5] >> (j & 31)) & 1u)) sel[P++] = j;
                ++j;
            }
        }
        __syncthreads();
        if (tid < CAPA) act[tid] = sel[tid];
        __syncthreads();
    }

    // ====== overlaps -> argmax -> one-hot ===================================
    if (tid < NASM) scnt[tid] = 0;
    __syncthreads();
    if (tid < CAPA) atomicAdd(&scnt[act[tid] / CAPA], 1);
    __syncthreads();
    if (tid == 0){
        int bi = 0, bc = scnt[0];
        for (int a = 1; a < NASM; ++a){ if (scnt[a] > bc){ bc = scnt[a]; bi = a; } }
        sbesta = bi;
    }
    __syncthreads();
    if (tid < NASM) out[(size_t)b * NASM + tid] = (tid == sbesta) ? 1.0f : 0.0f;
}

// ---------------------------------------------------------------------------
extern "C" void kernel_launch(void* const* d_in, const int* in_sizes, int n_in,
                              void* d_out, int out_size)
{
    const int*   p     = (const int*)d_in[0];     // [256]
    const int*   s     = (const int*)d_in[1];     // [64]
    const int*   k     = (const int*)d_in[2];     // [64]
    const float* W_in  = (const float*)d_in[3];   // [7680*7680]
    const float* W_rec = (const float*)d_in[4];   // [7680*7680]
    float*       out   = (float*)d_out;           // [64*256]

    prep_kernel<<<S1BLK + NASM, 128>>>(p, s, W_in, W_rec);
    pointer_ac_kernel<<<BATCH, NTM>>>(p, k, W_rec, out);
}

// round 6
// speedup vs baseline: 1.9194x; 1.0429x over previous
#include <cuda_runtime.h>
#include <cstdint>

#define NN     7680
#define NASM   256
#define CAPA   30
#define BATCH  64
#define KMAX   8
#define NTM    512
#define RPTM   15      // NN / NTM
#define MAXC   960
#define S1BLK  960     // step1: 15 chunks x 64 samples
#define CNBLK  256     // colnorm: one block per dst assembly
#define RBBLK  1920    // rowbits: 4 rows per block (warp per row)

__device__ float         g_invc[NN];
__device__ unsigned char g_scores8[BATCH][NN];
__device__ unsigned int  g_rowbits[NN];

static __device__ __forceinline__ unsigned long long make_key(float v, int j){
    // v > 0. Bigger value -> bigger key; equal value -> smaller j wins.
    return (((unsigned long long)__float_as_uint(v)) << 32) | (unsigned int)(NN - 1 - j);
}
static __device__ __forceinline__ int key_j(unsigned long long k){
    return NN - 1 - (int)(k & 0xffffffffull);
}

// ---------------------------------------------------------------------------
// Fused prep:
//  blocks [0,960):      step1 scores (uint8 exact counts)
//  blocks [960,1216):   colnorm -> g_invc
//  blocks [1216,3136):  row bitmasks of W_rec restricted to target assembly
// ---------------------------------------------------------------------------
__global__ void __launch_bounds__(128) prep_kernel(
    const int* __restrict__ p, const int* __restrict__ s,
    const float* __restrict__ W_in, const float* __restrict__ W_rec)
{
    const int bid = blockIdx.x;
    const int tid = threadIdx.x;
    if (bid < S1BLK){
        const int b  = bid / 15;
        const int c4 = (bid % 15) * 128 + tid;        // float4 index 0..1919
        const float4* src = (const float4*)(W_in + (size_t)__ldg(&s[b]) * CAPA * NN) + c4;
        float ax = 0.f, ay = 0.f, az = 0.f, aw = 0.f;
        #pragma unroll
        for (int m = 0; m < CAPA; ++m){
            float4 w = __ldg(src + (size_t)m * (NN / 4));
            ax += w.x; ay += w.y; az += w.z; aw += w.w;
        }
        uchar4 r;
        r.x = (unsigned char)(int)ax; r.y = (unsigned char)(int)ay;
        r.z = (unsigned char)(int)az; r.w = (unsigned char)(int)aw;
        ((uchar4*)g_scores8[b])[c4] = r;
    } else if (bid < S1BLK + CNBLK){
        __shared__ int   sp[NASM];
        __shared__ float acc[CAPA];
        const int a = bid - S1BLK;
        sp[tid]       = p[tid];
        sp[tid + 128] = p[tid + 128];
        if (tid < CAPA) acc[tid] = 0.f;
        __syncthreads();
        for (int q = 0; q < NASM; ++q){
            if (sp[q] == a){
                const float* base = W_rec + (size_t)q * CAPA * NN + a * CAPA;
                for (int i = tid; i < CAPA * CAPA; i += 128){
                    int m = i / CAPA, c = i % CAPA;
                    atomicAdd(&acc[c], __ldg(base + (size_t)m * NN + c));
                }
            }
        }
        __syncthreads();
        if (tid < CAPA) g_invc[a * CAPA + tid] = 1.0f / fmaxf(acc[tid], 1e-6f);
    } else {
        const int i    = (bid - S1BLK - CNBLK) * 4 + (tid >> 5);   // row 0..7679
        const int lane = tid & 31;
        const int a    = __ldg(&p[i / CAPA]);                      // target assembly
        float w = 0.f;
        if (lane < CAPA) w = __ldg(W_rec + (size_t)i * NN + a * CAPA + lane);
        unsigned bits = __ballot_sync(0xffffffffu, (lane < CAPA) && (w != 0.f));
        if (lane == 0) g_rowbits[i] = bits;
    }
}

// ---------------------------------------------------------------------------
// Main: one block per sample. Histogram kWTA + bitmask pointer-chase.
// ---------------------------------------------------------------------------
__global__ void __launch_bounds__(NTM) pointer_ac_kernel(
    const int* __restrict__ p, const int* __restrict__ k,
    float* __restrict__ out)
{
    __shared__ unsigned char sc8[NN];
    __shared__ unsigned long long cand[MAXC];
    __shared__ unsigned int bmap[NN / 32];
    __shared__ int   warpHist[16 * 31];
    __shared__ int   hist[31];
    __shared__ int   sp[NASM];
    __shared__ int   scnt[NASM];
    __shared__ unsigned char sflag[NASM];
    __shared__ int   act[CAPA];
    __shared__ int   stgt[CAPA];
    __shared__ unsigned int arb[CAPA];
    __shared__ int   sel[CAPA];
    __shared__ int   tgtl[CAPA];
    __shared__ int   warpSum[16], warpOff[16];
    __shared__ int   sT, sNG, sticket, sncand, sntgt, sbesta;

    const int b    = blockIdx.x;
    const int tid  = threadIdx.x;
    const int lane = tid & 31;
    const int wid  = tid >> 5;

    if (tid < NASM) sp[tid] = p[tid];
    const int kb = __ldg(&k[b]);
    if (tid < 16 * 31) warpHist[tid] = 0;
    if (tid == 0) sticket = 0;

    for (int i = tid; i < NN / 4; i += NTM)
        ((unsigned int*)sc8)[i] = ((const unsigned int*)g_scores8[b])[i];
    __syncthreads();

    // ====== dense kWTA via histogram (exact ints 0..30) =====================
    {
        int* myh = warpHist + wid * 31;
        const int base_j = tid * RPTM;                // contiguous segment
        #pragma unroll
        for (int i = 0; i < RPTM; ++i){
            int v = sc8[base_j + i];
            atomicAdd(&myh[v], 1);
        }
        __syncthreads();
        if (tid < 31){
            int c = 0;
            #pragma unroll
            for (int w = 0; w < 16; ++w) c += warpHist[w * 31 + tid];
            hist[tid] = c;
        }
        __syncthreads();
        if (tid == 0){
            int suf = 0, T = 0, ng = 0;
            for (int v = 30; v >= 0; --v){
                suf += hist[v];
                if (suf >= CAPA){ T = v; ng = suf - hist[v]; break; }
            }
            sT = T; sNG = ng;
        }
        __syncthreads();
        const int T    = sT;
        const int ng   = sNG;
        const int need = CAPA - ng;

        int cntT = 0;
        #pragma unroll
        for (int i = 0; i < RPTM; ++i) cntT += (sc8[base_j + i] == T);
        int incl = cntT;
        #pragma unroll
        for (int o = 1; o < 32; o <<= 1){
            int n = __shfl_up_sync(0xffffffffu, incl, o);
            if (lane >= o) incl += n;
        }
        if (lane == 31) warpSum[wid] = incl;
        __syncthreads();
        if (tid == 0){
            int run = 0;
            #pragma unroll
            for (int w = 0; w < 16; ++w){ warpOff[w] = run; run += warpSum[w]; }
        }
        __syncthreads();
        int slotT = warpOff[wid] + incl - cntT;

        #pragma unroll
        for (int i = 0; i < RPTM; ++i){
            int j = base_j + i;
            int v = sc8[j];
            if (v > T){
                int sl = atomicAdd(&sticket, 1);
                sel[sl] = j;
            } else if (v == T){
                if (slotT < need) sel[ng + slotT] = j;
                ++slotT;
            }
        }
        __syncthreads();
        if (tid < CAPA) act[tid] = sel[tid];
        __syncthreads();
    }

    // ====== recurrent pointer-chase (bitmask scoring, no W_rec gather) ======
    for (int t = 0; t < KMAX; ++t){
        if (t >= kb) break;                           // uniform per block

        if (tid < NASM) sflag[tid] = 0;
        if (tid < NN / 32) bmap[tid] = 0;
        if (tid == 0){ sncand = 0; sntgt = 0; }
        __syncthreads();
        if (tid < CAPA){
            int an = act[tid];
            int tg = sp[an / CAPA];
            stgt[tid] = tg;
            arb[tid]  = __ldg(&g_rowbits[an]);        // 30 parallel loads
            sflag[tg] = 1;
        }
        __syncthreads();
        if (tid < NASM && sflag[tid]){
            int pos = atomicAdd(&sntgt, 1);
            tgtl[pos] = tid;
        }
        __syncthreads();

        const int items = sntgt * CAPA;               // <= 900
        for (int i = tid; i < items; i += NTM){
            int a = tgtl[i / CAPA];
            int c = i % CAPA;
            int j = a * CAPA + c;
            float ic = __ldg(&g_invc[j]);
            float vv = 0.f;
            #pragma unroll
            for (int m = 0; m < CAPA; ++m){
                if (stgt[m] == a && ((arb[m] >> c) & 1u))
                    vv += ic;                          // same FP sequence as before
            }
            if (vv > 0.f){
                int slot = atomicAdd(&sncand, 1);
                cand[slot] = make_key(vv, j);
                atomicOr(&bmap[j >> 5], 1u << (j & 31));
            }
        }
        __syncthreads();

        const int nc = sncand;
        for (int q = tid; q < nc; q += NTM){
            unsigned long long kq = cand[q];
            int rank = 0;
            for (int x = 0; x < nc; ++x) rank += (cand[x] > kq);
            if (rank < CAPA) sel[rank] = key_j(kq);
        }
        __syncthreads();
        if (tid == 0 && nc < CAPA){
            int P = nc, j = 0;
            while (P < CAPA){
                if (!((bmap[j >> 5] >> (j & 31)) & 1u)) sel[P++] = j;
                ++j;
            }
        }
        __syncthreads();
        if (tid < CAPA) act[tid] = sel[tid];
        __syncthreads();
    }

    // ====== overlaps -> argmax -> one-hot ===================================
    if (tid < NASM) scnt[tid] = 0;
    __syncthreads();
    if (tid < CAPA) atomicAdd(&scnt[act[tid] / CAPA], 1);
    __syncthreads();
    if (tid == 0){
        int bi = 0, bc = scnt[0];
        for (int a = 1; a < NASM; ++a){ if (scnt[a] > bc){ bc = scnt[a]; bi = a; } }
        sbesta = bi;
    }
    __syncthreads();
    if (tid < NASM) out[(size_t)b * NASM + tid] = (tid == sbesta) ? 1.0f : 0.0f;
}

// ---------------------------------------------------------------------------
extern "C" void kernel_launch(void* const* d_in, const int* in_sizes, int n_in,
                              void* d_out, int out_size)
{
    const int*   p     = (const int*)d_in[0];     // [256]
    const int*   s     = (const int*)d_in[1];     // [64]
    const int*   k     = (const int*)d_in[2];     // [64]
    const float* W_in  = (const float*)d_in[3];   // [7680*7680]
    const float* W_rec = (const float*)d_in[4];   // [7680*7680]
    float*       out   = (float*)d_out;           // [64*256]

    prep_kernel<<<S1BLK + CNBLK + RBBLK, 128>>>(p, s, W_in, W_rec);
    pointer_ac_kernel<<<BATCH, NTM>>>(p, k, out);
}

// round 7
// speedup vs baseline: 2.0087x; 1.0465x over previous
#include <cuda_runtime.h>
#include <cstdint>

#define NN     7680
#define NASM   256
#define CAPA   30
#define BATCH  64
#define KMAX   8
#define NTM    256
#define RPTM   30      // NN / NTM
#define MAXC   960
#define S1BLK  960     // step1: 15 chunks x 64 samples
#define NN4    (NN / 4)

__device__ float         g_invc[NN];
__device__ unsigned char g_scores8[BATCH][NN];
__device__ unsigned int  g_rowbits[NN];

static __device__ __forceinline__ unsigned long long make_key(float v, int j){
    // v > 0. Bigger value -> bigger key; equal value -> smaller j wins.
    return (((unsigned long long)__float_as_uint(v)) << 32) | (unsigned int)(NN - 1 - j);
}
static __device__ __forceinline__ int key_j(unsigned long long k){
    return NN - 1 - (int)(k & 0xffffffffull);
}

// ---------------------------------------------------------------------------
// Fused prep:
//  blocks [0,960):      step1 scores (uint8 exact counts), 5-deep load batching
//  blocks [960,1216):   colnorm + rowbits (single read of the relevant patches)
// ---------------------------------------------------------------------------
__global__ void __launch_bounds__(128) prep_kernel(
    const int* __restrict__ p, const int* __restrict__ s,
    const float* __restrict__ W_in, const float* __restrict__ W_rec)
{
    const int bid = blockIdx.x;
    const int tid = threadIdx.x;
    if (bid < S1BLK){
        const int b  = bid / 15;
        const int c4 = (bid % 15) * 128 + tid;        // float4 index 0..1919
        const float4* src = (const float4*)(W_in + (size_t)__ldg(&s[b]) * CAPA * NN) + c4;
        float ax = 0.f, ay = 0.f, az = 0.f, aw = 0.f;
        #pragma unroll 1
        for (int g = 0; g < 6; ++g){                  // 5 loads in flight per group
            float4 w0 = __ldg(src + (size_t)(g * 5 + 0) * NN4);
            float4 w1 = __ldg(src + (size_t)(g * 5 + 1) * NN4);
            float4 w2 = __ldg(src + (size_t)(g * 5 + 2) * NN4);
            float4 w3 = __ldg(src + (size_t)(g * 5 + 3) * NN4);
            float4 w4 = __ldg(src + (size_t)(g * 5 + 4) * NN4);
            ax += w0.x + w1.x + w2.x + w3.x + w4.x;   // integer counts: exact any order
            ay += w0.y + w1.y + w2.y + w3.y + w4.y;
            az += w0.z + w1.z + w2.z + w3.z + w4.z;
            aw += w0.w + w1.w + w2.w + w3.w + w4.w;
        }
        uchar4 r;
        r.x = (unsigned char)(int)ax; r.y = (unsigned char)(int)ay;
        r.z = (unsigned char)(int)az; r.w = (unsigned char)(int)aw;
        ((uchar4*)g_scores8[b])[c4] = r;
    } else {
        // ---- colnorm + rowbits for destination assembly a ------------------
        __shared__ int      sp2[NASM];
        __shared__ int      cnt[CAPA];
        __shared__ unsigned rb[CAPA];
        const int a = bid - S1BLK;
        sp2[tid]       = p[tid];
        sp2[tid + 128] = p[tid + 128];
        if (tid < CAPA) cnt[tid] = 0;
        __syncthreads();
        for (int q = 0; q < NASM; ++q){
            if (sp2[q] == a){                         // block-uniform condition
                if (tid < CAPA) rb[tid] = 0;
                __syncthreads();
                for (int idx = tid; idx < CAPA * CAPA; idx += 128){
                    int m = idx / CAPA, c = idx % CAPA;
                    float w = __ldg(W_rec + (size_t)(q * CAPA + m) * NN + a * CAPA + c);
                    if (w != 0.f){
                        atomicAdd(&cnt[c], 1);
                        atomicOr(&rb[m], 1u << c);
                    }
                }
                __syncthreads();
                if (tid < CAPA) g_rowbits[q * CAPA + tid] = rb[tid];
                __syncthreads();
            }
        }
        if (tid < CAPA) g_invc[a * CAPA + tid] = 1.0f / fmaxf((float)cnt[tid], 1e-6f);
    }
}

// ---------------------------------------------------------------------------
// Main: one block per sample; 3 barriers per chase step.
// ---------------------------------------------------------------------------
__global__ void __launch_bounds__(NTM) pointer_ac_kernel(
    const int* __restrict__ p, const int* __restrict__ k,
    float* __restrict__ out)
{
    __shared__ unsigned int srb[NN];                  // cached rowbits (30 KB)
    __shared__ union {
        unsigned char sc8[NN];                        // kWTA phase
        unsigned long long cand[MAXC];                // chase phase
    } u;
    __shared__ unsigned int bmap[NN / 32];
    __shared__ int   warpHist[8 * 31];
    __shared__ int   hist[31];
    __shared__ int   sp[NASM];
    __shared__ int   scnt[NASM];
    __shared__ int   sel[CAPA];
    __shared__ int   tgtl[CAPA];
    __shared__ unsigned int smask[CAPA];
    __shared__ unsigned int arb[CAPA];
    __shared__ int   warpSum[8], warpOff[8];
    __shared__ int   sT, sNG, sticket, sncand, sntgt, sbesta;

    const int b    = blockIdx.x;
    const int tid  = threadIdx.x;
    const int lane = tid & 31;
    const int wid  = tid >> 5;

    sp[tid] = p[tid];
    const int kb = __ldg(&k[b]);
    if (tid < 8 * 31) warpHist[tid] = 0;
    if (tid == 0) sticket = 0;

    for (int i = tid; i < NN; i += NTM) srb[i] = g_rowbits[i];
    for (int i = tid; i < NN / 4; i += NTM)
        ((unsigned int*)u.sc8)[i] = ((const unsigned int*)g_scores8[b])[i];
    __syncthreads();

    // ====== dense kWTA via histogram (exact ints 0..30) =====================
    {
        int* myh = warpHist + wid * 31;
        const int base_j = tid * RPTM;                // contiguous segment
        #pragma unroll
        for (int i = 0; i < RPTM; ++i){
            int v = u.sc8[base_j + i];
            atomicAdd(&myh[v], 1);
        }
        __syncthreads();
        if (tid < 31){
            int c = 0;
            #pragma unroll
            for (int w = 0; w < 8; ++w) c += warpHist[w * 31 + tid];
            hist[tid] = c;
        }
        __syncthreads();
        if (tid == 0){
            int suf = 0, T = 0, ng = 0;
            for (int v = 30; v >= 0; --v){
                suf += hist[v];
                if (suf >= CAPA){ T = v; ng = suf - hist[v]; break; }
            }
            sT = T; sNG = ng;
        }
        __syncthreads();
        const int T    = sT;
        const int ng   = sNG;
        const int need = CAPA - ng;

        int cntT = 0;
        #pragma unroll
        for (int i = 0; i < RPTM; ++i) cntT += (u.sc8[base_j + i] == T);
        int incl = cntT;
        #pragma unroll
        for (int o = 1; o < 32; o <<= 1){
            int n = __shfl_up_sync(0xffffffffu, incl, o);
            if (lane >= o) incl += n;
        }
        if (lane == 31) warpSum[wid] = incl;
        __syncthreads();
        if (tid == 0){
            int run = 0;
            #pragma unroll
            for (int w = 0; w < 8; ++w){ warpOff[w] = run; run += warpSum[w]; }
        }
        __syncthreads();
        int slotT = warpOff[wid] + incl - cntT;

        #pragma unroll
        for (int i = 0; i < RPTM; ++i){
            int j = base_j + i;
            int v = u.sc8[j];
            if (v > T){
                int sl = atomicAdd(&sticket, 1);      // set order irrelevant
                sel[sl] = j;
            } else if (v == T){
                if (slotT < need) sel[ng + slotT] = j;
                ++slotT;
            }
        }
        __syncthreads();
    }

    // ====== recurrent pointer-chase: 3 barriers per step ====================
    for (int t = 0; t < KMAX; ++t){
        if (t >= kb) break;                           // uniform per block

        // Phase A: warp 0 dedups targets; other warps clear bmap
        if (wid == 0){
            int an = (lane < CAPA) ? sel[lane] : 0;
            int tg = (lane < CAPA) ? sp[an / CAPA] : (256 + lane);
            unsigned mm = __match_any_sync(0xffffffffu, tg);
            if (lane < CAPA) arb[lane] = srb[an];
            bool leader = (lane < CAPA) && ((int)(__ffs(mm) - 1) == lane);
            unsigned lb = __ballot_sync(0xffffffffu, leader);
            if (leader){
                int pos = __popc(lb & ((1u << lane) - 1u));
                tgtl[pos]  = tg;
                smask[pos] = mm;                      // source set for this target
            }
            if (lane == 0){ sntgt = __popc(lb); sncand = 0; }
        } else {
            for (int i = tid - 32; i < NN / 32; i += NTM - 32) bmap[i] = 0;
        }
        __syncthreads();

        // Phase B: score candidate columns (<= 900)
        const int items = sntgt * CAPA;
        for (int i = tid; i < items; i += NTM){
            int idx = i / CAPA, c = i % CAPA;
            int a = tgtl[idx];
            unsigned srcs = smask[idx];
            int j = a * CAPA + c;
            float ic = __ldg(&g_invc[j]);
            float vv = 0.f;
            while (srcs){                             // m ascending: same FP order
                int m = __ffs(srcs) - 1; srcs &= srcs - 1;
                if ((arb[m] >> c) & 1u) vv += ic;
            }
            if (vv > 0.f){
                int slot = atomicAdd(&sncand, 1);
                u.cand[slot] = make_key(vv, j);
                atomicOr(&bmap[j >> 5], 1u << (j & 31));
            }
        }
        __syncthreads();

        // Phase C: rank-select top-30 (+ smallest-index zero fill)
        const int nc = sncand;
        for (int q = tid; q < nc; q += NTM){
            unsigned long long kq = u.cand[q];
            int rank = 0;
            for (int x = 0; x < nc; ++x) rank += (u.cand[x] > kq);
            if (rank < CAPA) sel[rank] = key_j(kq);
        }
        if (tid == 0 && nc < CAPA){
            int P = nc, j = 0;
            while (P < CAPA){
                if (!((bmap[j >> 5] >> (j & 31)) & 1u)) sel[P++] = j;
                ++j;
            }
        }
        __syncthreads();
    }

    // ====== overlaps -> argmax -> one-hot ===================================
    scnt[tid] = 0;
    __syncthreads();
    if (tid < CAPA) atomicAdd(&scnt[sel[tid] / CAPA], 1);
    __syncthreads();
    if (tid == 0){
        int bi = 0, bc = scnt[0];
        for (int a = 1; a < NASM; ++a){ if (scnt[a] > bc){ bc = scnt[a]; bi = a; } }
        sbesta = bi;
    }
    __syncthreads();
    out[(size_t)b * NASM + tid] = (tid == sbesta) ? 1.0f : 0.0f;
}

// ---------------------------------------------------------------------------
extern "C" void kernel_launch(void* const* d_in, const int* in_sizes, int n_in,
                              void* d_out, int out_size)
{
    const int*   p     = (const int*)d_in[0];     // [256]
    const int*   s     = (const int*)d_in[1];     // [64]
    const int*   k     = (const int*)d_in[2];     // [64]
    const float* W_in  = (const float*)d_in[3];   // [7680*7680]
    const float* W_rec = (const float*)d_in[4];   // [7680*7680]
    float*       out   = (float*)d_out;           // [64*256]

    prep_kernel<<<S1BLK + NASM, 128>>>(p, s, W_in, W_rec);
    pointer_ac_kernel<<<BATCH, NTM>>>(p, k, out);
}

// round 8
// speedup vs baseline: 2.0576x; 1.0244x over previous
#include <cuda_runtime.h>
#include <cstdint>

#define NN     7680
#define NASM   256
#define CAPA   30
#define BATCH  64
#define KMAX   8
#define NTM    256
#define RPTM   30      // NN / NTM
#define MAXC   960
#define S1BLK  960     // step1: 15 chunks x 64 samples
#define NN4    (NN / 4)

__device__ float         g_invc[NN];
__device__ unsigned char g_scores8[BATCH][NN];
__device__ unsigned int  g_rowbits[NN];

static __device__ __forceinline__ unsigned long long make_key(float v, int j){
    // v > 0. Bigger value -> bigger key; equal value -> smaller j wins.
    return (((unsigned long long)__float_as_uint(v)) << 32) | (unsigned int)(NN - 1 - j);
}
static __device__ __forceinline__ int key_j(unsigned long long k){
    return NN - 1 - (int)(k & 0xffffffffull);
}

// ---------------------------------------------------------------------------
// Fused prep:
//  blocks [0,960):      step1 scores (uint8 exact counts), 10-deep load batching
//  blocks [960,1216):   colnorm + rowbits (single read of the relevant patches)
// ---------------------------------------------------------------------------
__global__ void __launch_bounds__(128) prep_kernel(
    const int* __restrict__ p, const int* __restrict__ s,
    const float* __restrict__ W_in, const float* __restrict__ W_rec)
{
    const int bid = blockIdx.x;
    const int tid = threadIdx.x;
    if (bid < S1BLK){
        const int b  = bid / 15;
        const int c4 = (bid % 15) * 128 + tid;        // float4 index 0..1919
        const float4* src = (const float4*)(W_in + (size_t)__ldg(&s[b]) * CAPA * NN) + c4;
        float ax = 0.f, ay = 0.f, az = 0.f, aw = 0.f;
        #pragma unroll 1
        for (int g = 0; g < 3; ++g){                  // 10 loads in flight per group
            float4 w[10];
            #pragma unroll
            for (int u = 0; u < 10; ++u)
                w[u] = __ldg(src + (size_t)(g * 10 + u) * NN4);
            #pragma unroll
            for (int u = 0; u < 10; ++u){             // integer counts: exact any order
                ax += w[u].x; ay += w[u].y; az += w[u].z; aw += w[u].w;
            }
        }
        uchar4 r;
        r.x = (unsigned char)(int)ax; r.y = (unsigned char)(int)ay;
        r.z = (unsigned char)(int)az; r.w = (unsigned char)(int)aw;
        ((uchar4*)g_scores8[b])[c4] = r;
    } else {
        // ---- colnorm + rowbits for destination assembly a ------------------
        __shared__ int      sp2[NASM];
        __shared__ int      cnt[CAPA];
        __shared__ unsigned rb[CAPA];
        const int a = bid - S1BLK;
        sp2[tid]       = p[tid];
        sp2[tid + 128] = p[tid + 128];
        if (tid < CAPA) cnt[tid] = 0;
        __syncthreads();
        for (int q = 0; q < NASM; ++q){
            if (sp2[q] == a){                         // block-uniform condition
                if (tid < CAPA) rb[tid] = 0;
                __syncthreads();
                for (int idx = tid; idx < CAPA * CAPA; idx += 128){
                    int m = idx / CAPA, c = idx % CAPA;
                    float w = __ldg(W_rec + (size_t)(q * CAPA + m) * NN + a * CAPA + c);
                    if (w != 0.f){
                        atomicAdd(&cnt[c], 1);
                        atomicOr(&rb[m], 1u << c);
                    }
                }
                __syncthreads();
                if (tid < CAPA) g_rowbits[q * CAPA + tid] = rb[tid];
                __syncthreads();
            }
        }
        if (tid < CAPA) g_invc[a * CAPA + tid] = 1.0f / fmaxf((float)cnt[tid], 1e-6f);
    }
}

// ---------------------------------------------------------------------------
// Main: one block per sample; invc cached in shared, rowbits read per step.
// ---------------------------------------------------------------------------
__global__ void __launch_bounds__(NTM) pointer_ac_kernel(
    const int* __restrict__ p, const int* __restrict__ k,
    float* __restrict__ out)
{
    __shared__ float sinvc[NN];                       // 30 KB: hot per-step array
    __shared__ union {
        unsigned char sc8[NN];                        // kWTA phase
        unsigned long long cand[MAXC];                // chase phase
    } u;
    __shared__ unsigned int bmap[NN / 32];
    __shared__ int   warpHist[8 * 31];
    __shared__ int   hist[31];
    __shared__ int   sp[NASM];
    __shared__ int   scnt[NASM];
    __shared__ int   sel[CAPA];
    __shared__ int   tgtl[CAPA];
    __shared__ unsigned int smask[CAPA];
    __shared__ unsigned int arb[CAPA];
    __shared__ int   warpSum[8], warpOff[8];
    __shared__ int   sT, sNG, sticket, sncand, sntgt, sbesta;

    const int b    = blockIdx.x;
    const int tid  = threadIdx.x;
    const int lane = tid & 31;
    const int wid  = tid >> 5;

    sp[tid] = p[tid];
    const int kb = __ldg(&k[b]);
    if (tid < 8 * 31) warpHist[tid] = 0;
    if (tid == 0) sticket = 0;

    for (int i = tid; i < NN4; i += NTM)              // float4: parallel, ~1 round
        ((float4*)sinvc)[i] = ((const float4*)g_invc)[i];
    for (int i = tid; i < NN / 16; i += NTM)          // uint4 score load
        ((uint4*)u.sc8)[i] = ((const uint4*)g_scores8[b])[i];
    __syncthreads();

    // ====== dense kWTA via histogram (exact ints 0..30) =====================
    {
        int* myh = warpHist + wid * 31;
        const int base_j = tid * RPTM;                // contiguous segment
        #pragma unroll
        for (int i = 0; i < RPTM; ++i){
            int v = u.sc8[base_j + i];
            atomicAdd(&myh[v], 1);
        }
        __syncthreads();
        if (tid < 31){
            int c = 0;
            #pragma unroll
            for (int w = 0; w < 8; ++w) c += warpHist[w * 31 + tid];
            hist[tid] = c;
        }
        __syncthreads();
        if (tid == 0){
            int suf = 0, T = 0, ng = 0;
            for (int v = 30; v >= 0; --v){
                suf += hist[v];
                if (suf >= CAPA){ T = v; ng = suf - hist[v]; break; }
            }
            sT = T; sNG = ng;
        }
        __syncthreads();
        const int T    = sT;
        const int ng   = sNG;
        const int need = CAPA - ng;

        int cntT = 0;
        #pragma unroll
        for (int i = 0; i < RPTM; ++i) cntT += (u.sc8[base_j + i] == T);
        int incl = cntT;
        #pragma unroll
        for (int o = 1; o < 32; o <<= 1){
            int n = __shfl_up_sync(0xffffffffu, incl, o);
            if (lane >= o) incl += n;
        }
        if (lane == 31) warpSum[wid] = incl;
        __syncthreads();
        if (tid == 0){
            int run = 0;
            #pragma unroll
            for (int w = 0; w < 8; ++w){ warpOff[w] = run; run += warpSum[w]; }
        }
        __syncthreads();
        int slotT = warpOff[wid] + incl - cntT;

        #pragma unroll
        for (int i = 0; i < RPTM; ++i){
            int j = base_j + i;
            int v = u.sc8[j];
            if (v > T){
                int sl = atomicAdd(&sticket, 1);      // set order irrelevant
                sel[sl] = j;
            } else if (v == T){
                if (slotT < need) sel[ng + slotT] = j;
                ++slotT;
            }
        }
        __syncthreads();
    }

    // ====== recurrent pointer-chase: 3 barriers per step ====================
    for (int t = 0; t < KMAX; ++t){
        if (t >= kb) break;                           // uniform per block

        // Phase A: warp 0 dedups targets + loads rowbits; others clear bmap
        if (wid == 0){
            int an = (lane < CAPA) ? sel[lane] : 0;
            int tg = (lane < CAPA) ? sp[an / CAPA] : (256 + lane);
            unsigned mm = __match_any_sync(0xffffffffu, tg);
            if (lane < CAPA) arb[lane] = __ldg(&g_rowbits[an]);   // 30 parallel L2 hits
            bool leader = (lane < CAPA) && ((int)(__ffs(mm) - 1) == lane);
            unsigned lb = __ballot_sync(0xffffffffu, leader);
            if (leader){
                int pos = __popc(lb & ((1u << lane) - 1u));
                tgtl[pos]  = tg;
                smask[pos] = mm;                      // source set for this target
            }
            if (lane == 0){ sntgt = __popc(lb); sncand = 0; }
        } else {
            for (int i = tid - 32; i < NN / 32; i += NTM - 32) bmap[i] = 0;
        }
        __syncthreads();

        // Phase B: score candidate columns (<= 900), invc from shared
        const int items = sntgt * CAPA;
        for (int i = tid; i < items; i += NTM){
            int idx = i / CAPA, c = i % CAPA;
            int a = tgtl[idx];
            unsigned srcs = smask[idx];
            int j = a * CAPA + c;
            float ic = sinvc[j];
            float vv = 0.f;
            while (srcs){                             // m ascending: same FP order
                int m = __ffs(srcs) - 1; srcs &= srcs - 1;
                if ((arb[m] >> c) & 1u) vv += ic;
            }
            if (vv > 0.f){
                int slot = atomicAdd(&sncand, 1);
                u.cand[slot] = make_key(vv, j);
                atomicOr(&bmap[j >> 5], 1u << (j & 31));
            }
        }
        __syncthreads();

        // Phase C: rank-select top-30 (+ smallest-index zero fill)
        const int nc = sncand;
        for (int q = tid; q < nc; q += NTM){
            unsigned long long kq = u.cand[q];
            int rank = 0;
            for (int x = 0; x < nc; ++x) rank += (u.cand[x] > kq);
            if (rank < CAPA) sel[rank] = key_j(kq);
        }
        if (tid == 0 && nc < CAPA){
            int P = nc, j = 0;
            while (P < CAPA){
                if (!((bmap[j >> 5] >> (j & 31)) & 1u)) sel[P++] = j;
                ++j;
            }
        }
        __syncthreads();
    }

    // ====== overlaps -> argmax (warp 0 reduce) -> one-hot ===================
    scnt[tid] = 0;
    __syncthreads();
    if (tid < CAPA) atomicAdd(&scnt[sel[tid] / CAPA], 1);
    __syncthreads();
    if (wid == 0){
        unsigned long long bk = 0;
        #pragma unroll
        for (int r = 0; r < NASM / 32; ++r){
            int a = lane + r * 32;
            unsigned long long key =
                (((unsigned long long)scnt[a]) << 32) | (unsigned)(NASM - 1 - a);
            if (key > bk) bk = key;                   // max count, then smallest a
        }
        #pragma unroll
        for (int o = 16; o > 0; o >>= 1){
            unsigned long long obk = __shfl_xor_sync(0xffffffffu, bk, o);
            if (obk > bk) bk = obk;
        }
        if (lane == 0) sbesta = NASM - 1 - (int)(bk & 0xffffffffull);
    }
    __syncthreads();
    out[(size_t)b * NASM + tid] = (tid == sbesta) ? 1.0f : 0.0f;
}

// ---------------------------------------------------------------------------
extern "C" void kernel_launch(void* const* d_in, const int* in_sizes, int n_in,
                              void* d_out, int out_size)
{
    const int*   p     = (const int*)d_in[0];     // [256]
    const int*   s     = (const int*)d_in[1];     // [64]
    const int*   k     = (const int*)d_in[2];     // [64]
    const float* W_in  = (const float*)d_in[3];   // [7680*7680]
    const float* W_rec = (const float*)d_in[4];   // [7680*7680]
    float*       out   = (float*)d_out;           // [64*256]

    prep_kernel<<<S1BLK + NASM, 128>>>(p, s, W_in, W_rec);
    pointer_ac_kernel<<<BATCH, NTM>>>(p, k, out);
}

// round 9
// speedup vs baseline: 2.0725x; 1.0073x over previous
#include <cuda_runtime.h>
#include <cstdint>

#define NN     7680
#define NASM   256
#define CAPA   30
#define BATCH  64
#define KMAX   8
#define NTM    256
#define RPTM   30      // NN / NTM
#define MAXC   960
#define S1BLK  960     // step1: 15 chunks x 64 samples
#define NN4    (NN / 4)

__device__ float         g_invc[NN];
__device__ unsigned char g_scores8[BATCH][NN];
__device__ unsigned int  g_rowbits[NN];

static __device__ __forceinline__ unsigned long long make_key(float v, int j){
    // v > 0. Bigger value -> bigger key; equal value -> smaller j wins.
    return (((unsigned long long)__float_as_uint(v)) << 32) | (unsigned int)(NN - 1 - j);
}
static __device__ __forceinline__ int key_j(unsigned long long k){
    return NN - 1 - (int)(k & 0xffffffffull);
}

// ---------------------------------------------------------------------------
// Fused prep:
//  blocks [0,960):      step1 scores (uint8 exact counts)
//  blocks [960,1216):   colnorm + rowbits
// ---------------------------------------------------------------------------
__global__ void __launch_bounds__(128) prep_kernel(
    const int* __restrict__ p, const int* __restrict__ s,
    const float* __restrict__ W_in, const float* __restrict__ W_rec)
{
    const int bid = blockIdx.x;
    const int tid = threadIdx.x;
    if (bid < S1BLK){
        const int b  = bid / 15;
        const int c4 = (bid % 15) * 128 + tid;        // float4 index 0..1919
        const float4* src = (const float4*)(W_in + (size_t)__ldg(&s[b]) * CAPA * NN) + c4;
        float ax = 0.f, ay = 0.f, az = 0.f, aw = 0.f;
        #pragma unroll 1
        for (int g = 0; g < 3; ++g){                  // 10 loads in flight per group
            float4 w[10];
            #pragma unroll
            for (int uu = 0; uu < 10; ++uu)
                w[uu] = __ldg(src + (size_t)(g * 10 + uu) * NN4);
            #pragma unroll
            for (int uu = 0; uu < 10; ++uu){          // integer counts: exact any order
                ax += w[uu].x; ay += w[uu].y; az += w[uu].z; aw += w[uu].w;
            }
        }
        uchar4 r;
        r.x = (unsigned char)(int)ax; r.y = (unsigned char)(int)ay;
        r.z = (unsigned char)(int)az; r.w = (unsigned char)(int)aw;
        ((uchar4*)g_scores8[b])[c4] = r;
    } else {
        // ---- colnorm + rowbits for destination assembly a ------------------
        __shared__ int      sp2[NASM];
        __shared__ int      cnt[CAPA];
        __shared__ unsigned rb[CAPA];
        const int a = bid - S1BLK;
        sp2[tid]       = p[tid];
        sp2[tid + 128] = p[tid + 128];
        if (tid < CAPA) cnt[tid] = 0;
        __syncthreads();
        for (int q = 0; q < NASM; ++q){
            if (sp2[q] == a){                         // block-uniform condition
                if (tid < CAPA) rb[tid] = 0;
                __syncthreads();
                for (int idx = tid; idx < CAPA * CAPA; idx += 128){
                    int m = idx / CAPA, c = idx % CAPA;
                    float w = __ldg(W_rec + (size_t)(q * CAPA + m) * NN + a * CAPA + c);
                    if (w != 0.f){
                        atomicAdd(&cnt[c], 1);
                        atomicOr(&rb[m], 1u << c);
                    }
                }
                __syncthreads();
                if (tid < CAPA) g_rowbits[q * CAPA + tid] = rb[tid];
                __syncthreads();
            }
        }
        if (tid < CAPA) g_invc[a * CAPA + tid] = 1.0f / fmaxf((float)cnt[tid], 1e-6f);
    }
}

// ---------------------------------------------------------------------------
// Main: one block per sample; vector Phase B (lane = column).
// ---------------------------------------------------------------------------
__global__ void __launch_bounds__(NTM) pointer_ac_kernel(
    const int* __restrict__ p, const int* __restrict__ k,
    float* __restrict__ out)
{
    __shared__ float sinvc[NN];                       // 30 KB
    __shared__ union {
        unsigned char sc8[NN];                        // kWTA phase
        unsigned long long cand[MAXC];                // chase phase
    } u;
    __shared__ int   warpHist[8 * 31];
    __shared__ int   hist[31];
    __shared__ int   sp[NASM];
    __shared__ int   scnt[NASM];
    __shared__ int   sel[CAPA];
    __shared__ int   tgtl[CAPA];
    __shared__ unsigned int smask[CAPA];
    __shared__ unsigned int arb[CAPA];
    __shared__ int   warpSum[8], warpOff[8];
    __shared__ int   sT, sNG, sticket, sncand, sntgt, sbesta;

    const int b    = blockIdx.x;
    const int tid  = threadIdx.x;
    const int lane = tid & 31;
    const int wid  = tid >> 5;

    sp[tid] = p[tid];
    const int kb = __ldg(&k[b]);
    if (tid < 8 * 31) warpHist[tid] = 0;
    if (tid == 0) sticket = 0;

    #pragma unroll
    for (int r = 0; r < NN4 / NTM + 1; ++r){          // float4 invc cache
        int i = tid + r * NTM;
        if (i < NN4) ((float4*)sinvc)[i] = ((const float4*)g_invc)[i];
    }
    #pragma unroll
    for (int r = 0; r < 2; ++r){                      // uint4 score load
        int i = tid + r * NTM;
        if (i < NN / 16) ((uint4*)u.sc8)[i] = ((const uint4*)g_scores8[b])[i];
    }
    __syncthreads();

    // ====== dense kWTA via histogram (exact ints 0..30) =====================
    {
        int* myh = warpHist + wid * 31;
        const int base_j = tid * RPTM;                // contiguous segment
        #pragma unroll
        for (int i = 0; i < RPTM; ++i){
            int v = u.sc8[base_j + i];
            atomicAdd(&myh[v], 1);
        }
        __syncthreads();
        if (tid < 31){
            int c = 0;
            #pragma unroll
            for (int w = 0; w < 8; ++w) c += warpHist[w * 31 + tid];
            hist[tid] = c;
        }
        __syncthreads();
        if (tid == 0){
            int suf = 0, T = 0, ng = 0;
            for (int v = 30; v >= 0; --v){
                suf += hist[v];
                if (suf >= CAPA){ T = v; ng = suf - hist[v]; break; }
            }
            sT = T; sNG = ng;
        }
        __syncthreads();
        const int T    = sT;
        const int ng   = sNG;
        const int need = CAPA - ng;

        int cntT = 0;
        #pragma unroll
        for (int i = 0; i < RPTM; ++i) cntT += (u.sc8[base_j + i] == T);
        int incl = cntT;
        #pragma unroll
        for (int o = 1; o < 32; o <<= 1){
            int n = __shfl_up_sync(0xffffffffu, incl, o);
            if (lane >= o) incl += n;
        }
        if (lane == 31) warpSum[wid] = incl;
        __syncthreads();
        if (tid == 0){
            int run = 0;
            #pragma unroll
            for (int w = 0; w < 8; ++w){ warpOff[w] = run; run += warpSum[w]; }
        }
        __syncthreads();
        int slotT = warpOff[wid] + incl - cntT;

        #pragma unroll
        for (int i = 0; i < RPTM; ++i){
            int j = base_j + i;
            int v = u.sc8[j];
            if (v > T){
                int sl = atomicAdd(&sticket, 1);      // set order irrelevant
                sel[sl] = j;
            } else if (v == T){
                if (slotT < need) sel[ng + slotT] = j;
                ++slotT;
            }
        }
        __syncthreads();
    }

    // ====== recurrent pointer-chase: 3 light barriers per step ==============
    for (int t = 0; t < KMAX; ++t){
        if (t >= kb) break;                           // uniform per block

        // Phase A (warp 0): dedup targets, load rowbits
        if (wid == 0){
            int an = (lane < CAPA) ? sel[lane] : 0;
            int tg = (lane < CAPA) ? sp[an / CAPA] : (256 + lane);
            unsigned mm = __match_any_sync(0xffffffffu, tg);
            if (lane < CAPA) arb[lane] = __ldg(&g_rowbits[an]);   // 30 parallel L2
            bool leader = (lane < CAPA) && ((int)(__ffs(mm) - 1) == lane);
            unsigned lb = __ballot_sync(0xffffffffu, leader);
            if (leader){
                int pos = __popc(lb & ((1u << lane) - 1u));
                tgtl[pos]  = tg;
                smask[pos] = mm;                      // source set for this target
            }
            if (lane == 0){ sntgt = __popc(lb); sncand = 0; }
        }
        __syncthreads();

        // Phase B: lane = column; warps stride over targets (<=30)
        const int ntg = sntgt;
        for (int idx = wid; idx < ntg; idx += 8){
            int a = tgtl[idx];
            unsigned srcs = smask[idx];
            int j = a * CAPA + lane;
            float ic = (lane < CAPA) ? sinvc[j] : 0.f;
            float vv = 0.f;
            while (srcs){                             // m ascending: same FP order
                int m = __ffs(srcs) - 1; srcs &= srcs - 1;
                if ((arb[m] >> lane) & 1u) vv += ic;  // lanes 30/31: bit always 0
            }
            bool pos = (lane < CAPA) && (vv > 0.f);
            unsigned bal = __ballot_sync(0xffffffffu, pos);
            if (bal){
                int ldr = __ffs(bal) - 1;
                int base = 0;
                if (lane == ldr) base = atomicAdd(&sncand, __popc(bal));
                base = __shfl_sync(0xffffffffu, base, ldr);
                if (pos) u.cand[base + __popc(bal & ((1u << lane) - 1u))] = make_key(vv, j);
            }
        }
        __syncthreads();

        // Phase C: rank-select top-30 (+ smallest-index zero fill)
        const int nc = sncand;
        for (int q = tid; q < nc; q += NTM){
            unsigned long long kq = u.cand[q];
            int rank = 0;
            for (int x = 0; x < nc; ++x) rank += (u.cand[x] > kq);
            if (rank < CAPA) sel[rank] = key_j(kq);
        }
        if (tid == 0 && nc < CAPA){
            int P = nc, j = 0;
            while (P < CAPA){
                bool ispos = false;
                for (int x = 0; x < nc; ++x) ispos |= (key_j(u.cand[x]) == j);
                if (!ispos) sel[P++] = j;
                ++j;
            }
        }
        __syncthreads();
    }

    // ====== overlaps -> argmax (warp 0 reduce) -> one-hot ===================
    scnt[tid] = 0;
    __syncthreads();
    if (tid < CAPA) atomicAdd(&scnt[sel[tid] / CAPA], 1);
    __syncthreads();
    if (wid == 0){
        unsigned long long bk = 0;
        #pragma unroll
        for (int r = 0; r < NASM / 32; ++r){
            int a = lane + r * 32;
            unsigned long long key =
                (((unsigned long long)scnt[a]) << 32) | (unsigned)(NASM - 1 - a);
            if (key > bk) bk = key;                   // max count, then smallest a
        }
        #pragma unroll
        for (int o = 16; o > 0; o >>= 1){
            unsigned long long obk = __shfl_xor_sync(0xffffffffu, bk, o);
            if (obk > bk) bk = obk;
        }
        if (lane == 0) sbesta = NASM - 1 - (int)(bk & 0xffffffffull);
    }
    __syncthreads();
    out[(size_t)b * NASM + tid] = (tid == sbesta) ? 1.0f : 0.0f;
}

// ---------------------------------------------------------------------------
extern "C" void kernel_launch(void* const* d_in, const int* in_sizes, int n_in,
                              void* d_out, int out_size)
{
    const int*   p     = (const int*)d_in[0];     // [256]
    const int*   s     = (const int*)d_in[1];     // [64]
    const int*   k     = (const int*)d_in[2];     // [64]
    const float* W_in  = (const float*)d_in[3];   // [7680*7680]
    const float* W_rec = (const float*)d_in[4];   // [7680*7680]
    float*       out   = (float*)d_out;           // [64*256]

    prep_kernel<<<S1BLK + NASM, 128>>>(p, s, W_in, W_rec);
    pointer_ac_kernel<<<BATCH, NTM>>>(p, k, out);
}

// round 12
// speedup vs baseline: 2.2306x; 1.0763x over previous
#include <cuda_runtime.h>
#include <cstdint>

#define NN     7680
#define NASM   256
#define CAPA   30
#define BATCH  64
#define KMAX   8
#define NTM    512
#define RPTM   15      // NN / NTM
#define NWARP  16
#define MAXC   960
#define S1BLK  960     // step1: 15 chunks x 64 samples
#define NN4    (NN / 4)

// dynamic smem layout (bytes): [0,7680) cand/sc8 union, [7680,38400) sinvc,
// [38400,69120) srb
#define SMEM_DYN_BYTES (7680 + 30720 + 30720)

__device__ float         g_invc[NN];
__device__ unsigned char g_scores8[BATCH][NN];
__device__ unsigned int  g_rowbits[NN];

static __device__ __forceinline__ unsigned long long make_key(float v, int j){
    // v > 0. Bigger value -> bigger key; equal value -> smaller j wins.
    return (((unsigned long long)__float_as_uint(v)) << 32) | (unsigned int)(NN - 1 - j);
}
static __device__ __forceinline__ int key_j(unsigned long long k){
    return NN - 1 - (int)(k & 0xffffffffull);
}

// ---------------------------------------------------------------------------
// Fused prep:
//  blocks [0,960):      step1 scores (uint8 exact counts)
//  blocks [960,1216):   colnorm + rowbits
// ---------------------------------------------------------------------------
__global__ void __launch_bounds__(128) prep_kernel(
    const int* __restrict__ p, const int* __restrict__ s,
    const float* __restrict__ W_in, const float* __restrict__ W_rec)
{
    const int bid = blockIdx.x;
    const int tid = threadIdx.x;
    if (bid < S1BLK){
        const int b  = bid / 15;
        const int c4 = (bid % 15) * 128 + tid;        // float4 index 0..1919
        const float4* src = (const float4*)(W_in + (size_t)__ldg(&s[b]) * CAPA * NN) + c4;
        float ax = 0.f, ay = 0.f, az = 0.f, aw = 0.f;
        #pragma unroll 1
        for (int g = 0; g < 3; ++g){                  // 10 loads in flight per group
            float4 w[10];
            #pragma unroll
            for (int uu = 0; uu < 10; ++uu)
                w[uu] = __ldg(src + (size_t)(g * 10 + uu) * NN4);
            #pragma unroll
            for (int uu = 0; uu < 10; ++uu){          // integer counts: exact any order
                ax += w[uu].x; ay += w[uu].y; az += w[uu].z; aw += w[uu].w;
            }
        }
        uchar4 r;
        r.x = (unsigned char)(int)ax; r.y = (unsigned char)(int)ay;
        r.z = (unsigned char)(int)az; r.w = (unsigned char)(int)aw;
        ((uchar4*)g_scores8[b])[c4] = r;
    } else {
        // ---- colnorm + rowbits for destination assembly a ------------------
        __shared__ int      sp2[NASM];
        __shared__ int      cnt[CAPA];
        __shared__ unsigned rb[CAPA];
        const int a = bid - S1BLK;
        sp2[tid]       = p[tid];
        sp2[tid + 128] = p[tid + 128];
        if (tid < CAPA) cnt[tid] = 0;
        __syncthreads();
        for (int q = 0; q < NASM; ++q){
            if (sp2[q] == a){                         // block-uniform condition
                if (tid < CAPA) rb[tid] = 0;
                __syncthreads();
                for (int idx = tid; idx < CAPA * CAPA; idx += 128){
                    int m = idx / CAPA, c = idx % CAPA;
                    float w = __ldg(W_rec + (size_t)(q * CAPA + m) * NN + a * CAPA + c);
                    if (w != 0.f){
                        atomicAdd(&cnt[c], 1);
                        atomicOr(&rb[m], 1u << c);
                    }
                }
                __syncthreads();
                if (tid < CAPA) g_rowbits[q * CAPA + tid] = rb[tid];
                __syncthreads();
            }
        }
        if (tid < CAPA) g_invc[a * CAPA + tid] = 1.0f / fmaxf((float)cnt[tid], 1e-6f);
    }
}

// ---------------------------------------------------------------------------
// Main: one block per sample; 512 threads; hot arrays in dynamic shared.
// ---------------------------------------------------------------------------
__global__ void __launch_bounds__(NTM) pointer_ac_kernel(
    const int* __restrict__ p, const int* __restrict__ k,
    float* __restrict__ out)
{
    extern __shared__ char dyn[];
    unsigned long long* cand = (unsigned long long*)dyn;      // [MAXC], chase phase
    unsigned char*      sc8  = (unsigned char*)dyn;           // [NN], kWTA phase (union)
    float*              sinvc = (float*)(dyn + 7680);         // [NN]
    unsigned int*       srb   = (unsigned int*)(dyn + 38400); // [NN]

    __shared__ int   warpHist[NWARP * 31];
    __shared__ int   hist[31];
    __shared__ int   sp[NASM];
    __shared__ int   scnt[NASM];
    __shared__ int   sel[CAPA];
    __shared__ int   tgtl[CAPA];
    __shared__ unsigned int smask[CAPA];
    __shared__ unsigned int arb[CAPA];
    __shared__ int   warpSum[NWARP], warpOff[NWARP];
    __shared__ int   sT, sNG, sticket, sncand, sntgt, sbesta;

    const int b    = blockIdx.x;
    const int tid  = threadIdx.x;
    const int lane = tid & 31;
    const int wid  = tid >> 5;

    if (tid < NASM) sp[tid] = p[tid];
    const int kb = __ldg(&k[b]);
    if (tid < NWARP * 31) warpHist[tid] = 0;
    if (tid == 0) sticket = 0;

    // vectorized shared-cache loads (correct bounds!)
    #pragma unroll
    for (int r = 0; r < 4; ++r){                      // sinvc: 1920 float4
        int i = tid + r * NTM;
        if (i < NN4) ((float4*)sinvc)[i] = ((const float4*)g_invc)[i];
    }
    #pragma unroll
    for (int r = 0; r < 4; ++r){                      // srb: 1920 uint4
        int i = tid + r * NTM;
        if (i < NN4) ((uint4*)srb)[i] = ((const uint4*)g_rowbits)[i];
    }
    if (tid < NN / 16)                                // sc8: 480 uint4 (byte array)
        ((uint4*)sc8)[tid] = ((const uint4*)g_scores8[b])[tid];
    __syncthreads();

    // ====== dense kWTA via histogram (exact ints 0..30) =====================
    {
        int* myh = warpHist + wid * 31;
        const int base_j = tid * RPTM;                // contiguous segment
        #pragma unroll
        for (int i = 0; i < RPTM; ++i){
            int v = sc8[base_j + i];
            atomicAdd(&myh[v], 1);
        }
        __syncthreads();
        if (tid < 31){
            int c = 0;
            #pragma unroll
            for (int w = 0; w < NWARP; ++w) c += warpHist[w * 31 + tid];
            hist[tid] = c;
        }
        __syncthreads();
        if (tid == 0){
            int suf = 0, T = 0, ng = 0;
            for (int v = 30; v >= 0; --v){
                suf += hist[v];
                if (suf >= CAPA){ T = v; ng = suf - hist[v]; break; }
            }
            sT = T; sNG = ng;
        }
        __syncthreads();
        const int T    = sT;
        const int ng   = sNG;
        const int need = CAPA - ng;

        int cntT = 0;
        #pragma unroll
        for (int i = 0; i < RPTM; ++i) cntT += (sc8[base_j + i] == T);
        int incl = cntT;
        #pragma unroll
        for (int o = 1; o < 32; o <<= 1){
            int n = __shfl_up_sync(0xffffffffu, incl, o);
            if (lane >= o) incl += n;
        }
        if (lane == 31) warpSum[wid] = incl;
        __syncthreads();
        if (tid == 0){
            int run = 0;
            #pragma unroll
            for (int w = 0; w < NWARP; ++w){ warpOff[w] = run; run += warpSum[w]; }
        }
        __syncthreads();
        int slotT = warpOff[wid] + incl - cntT;

        #pragma unroll
        for (int i = 0; i < RPTM; ++i){
            int j = base_j + i;
            int v = sc8[j];
            if (v > T){
                int sl = atomicAdd(&sticket, 1);      // set order irrelevant
                sel[sl] = j;
            } else if (v == T){
                if (slotT < need) sel[ng + slotT] = j;
                ++slotT;
            }
        }
        __syncthreads();
    }

    // ====== recurrent pointer-chase: 3 light barriers per step ==============
    for (int t = 0; t < KMAX; ++t){
        if (t >= kb) break;                           // uniform per block

        // Phase A (warp 0): dedup targets, rowbits from shared
        if (wid == 0){
            int an = (lane < CAPA) ? sel[lane] : 0;
            int tg = (lane < CAPA) ? sp[an / CAPA] : (256 + lane);
            unsigned mm = __match_any_sync(0xffffffffu, tg);
            if (lane < CAPA) arb[lane] = srb[an];     // LDS only
            bool leader = (lane < CAPA) && ((int)(__ffs(mm) - 1) == lane);
            unsigned lb = __ballot_sync(0xffffffffu, leader);
            if (leader){
                int pos = __popc(lb & ((1u << lane) - 1u));
                tgtl[pos]  = tg;
                smask[pos] = mm;                      // source set for this target
            }
            if (lane == 0){ sntgt = __popc(lb); sncand = 0; }
        }
        __syncthreads();

        // Phase B: lane = column; warps stride over targets (<=30)
        const int ntg = sntgt;
        for (int idx = wid; idx < ntg; idx += NWARP){
            int a = tgtl[idx];
            unsigned srcs = smask[idx];
            int j = a * CAPA + lane;
            float ic = (lane < CAPA) ? sinvc[j] : 0.f;
            float vv = 0.f;
            while (srcs){                             // m ascending: same FP order
                int m = __ffs(srcs) - 1; srcs &= srcs - 1;
                if ((arb[m] >> lane) & 1u) vv += ic;  // lanes 30/31: bit always 0
            }
            bool pos = (lane < CAPA) && (vv > 0.f);
            unsigned bal = __ballot_sync(0xffffffffu, pos);
            if (bal){
                int ldr = __ffs(bal) - 1;
                int base = 0;
                if (lane == ldr) base = atomicAdd(&sncand, __popc(bal));
                base = __shfl_sync(0xffffffffu, base, ldr);
                if (pos) cand[base + __popc(bal & ((1u << lane) - 1u))] = make_key(vv, j);
            }
        }
        __syncthreads();

        // Phase C: rank-select top-30 (+ smallest-index zero fill)
        const int nc = sncand;
        for (int q = tid; q < nc; q += NTM){
            unsigned long long kq = cand[q];
            int rank = 0;
            for (int x = 0; x < nc; ++x) rank += (cand[x] > kq);
            if (rank < CAPA) sel[rank] = key_j(kq);
        }
        if (tid == 0 && nc < CAPA){
            int P = nc, j = 0;
            while (P < CAPA){
                bool ispos = false;
                for (int x = 0; x < nc; ++x) ispos |= (key_j(cand[x]) == j);
                if (!ispos) sel[P++] = j;
                ++j;
            }
        }
        __syncthreads();
    }

    // ====== overlaps -> argmax (warp 0 reduce) -> one-hot ===================
    if (tid < NASM) scnt[tid] = 0;
    __syncthreads();
    if (tid < CAPA) atomicAdd(&scnt[sel[tid] / CAPA], 1);
    __syncthreads();
    if (wid == 0){
        unsigned long long bk = 0;
        #pragma unroll
        for (int r = 0; r < NASM / 32; ++r){
            int a = lane + r * 32;
            unsigned long long key =
                (((unsigned long long)scnt[a]) << 32) | (unsigned)(NASM - 1 - a);
            if (key > bk) bk = key;                   // max count, then smallest a
        }
        #pragma unroll
        for (int o = 16; o > 0; o >>= 1){
            unsigned long long obk = __shfl_xor_sync(0xffffffffu, bk, o);
            if (obk > bk) bk = obk;
        }
        if (lane == 0) sbesta = NASM - 1 - (int)(bk & 0xffffffffull);
    }
    __syncthreads();
    if (tid < NASM) out[(size_t)b * NASM + tid] = (tid == sbesta) ? 1.0f : 0.0f;
}

// ---------------------------------------------------------------------------
extern "C" void kernel_launch(void* const* d_in, const int* in_sizes, int n_in,
                              void* d_out, int out_size)
{
    const int*   p     = (const int*)d_in[0];     // [256]
    const int*   s     = (const int*)d_in[1];     // [64]
    const int*   k     = (const int*)d_in[2];     // [64]
    const float* W_in  = (const float*)d_in[3];   // [7680*7680]
    const float* W_rec = (const float*)d_in[4];   // [7680*7680]
    float*       out   = (float*)d_out;           // [64*256]

    cudaFuncSetAttribute(pointer_ac_kernel,
                         cudaFuncAttributeMaxDynamicSharedMemorySize, SMEM_DYN_BYTES);
    prep_kernel<<<S1BLK + NASM, 128>>>(p, s, W_in, W_rec);
    pointer_ac_kernel<<<BATCH, NTM, SMEM_DYN_BYTES>>>(p, k, out);
}

// round 13
// speedup vs baseline: 3.4105x; 1.5289x over previous
#include <cuda_runtime.h>
#include <cstdint>

#define NN     7680
#define NASM   256
#define CAPA   30
#define BATCH  64
#define KMAX   8
#define NTM    512
#define RPTM   15      // NN / NTM
#define NWARP  16
#define MAXC   960
#define S1BLK  960     // step1: 15 chunks x 64 samples
#define NN4    (NN / 4)
#define QCH    8       // colnorm source-chunk

// dynamic smem layout (bytes): [0,7680) cand/sc8 union, [7680,38400) sinvc,
// [38400,69120) srb
#define SMEM_DYN_BYTES (7680 + 30720 + 30720)

__device__ float         g_invc[NN];
__device__ unsigned char g_scores8[BATCH][NN];
__device__ unsigned int  g_rowbits[NN];

static __device__ __forceinline__ unsigned long long make_key(float v, int j){
    // v > 0. Bigger value -> bigger key; equal value -> smaller j wins.
    return (((unsigned long long)__float_as_uint(v)) << 32) | (unsigned int)(NN - 1 - j);
}
static __device__ __forceinline__ int key_j(unsigned long long k){
    return NN - 1 - (int)(k & 0xffffffffull);
}

// ---------------------------------------------------------------------------
// Fused prep:
//  blocks [0,960):      step1 scores (uint8 exact counts), dedup by s[b]
//  blocks [960,1216):   colnorm + rowbits, gather-parallel
// ---------------------------------------------------------------------------
__global__ void __launch_bounds__(128) prep_kernel(
    const int* __restrict__ p, const int* __restrict__ s,
    const float* __restrict__ W_in, const float* __restrict__ W_rec)
{
    const int bid = blockIdx.x;
    const int tid = threadIdx.x;
    if (bid < S1BLK){
        __shared__ int ss[BATCH];
        const int b = bid / 15;
        if (tid < BATCH) ss[tid] = s[tid];
        __syncthreads();
        const int sb = ss[b];
        bool dup = false;
        for (int b2 = 0; b2 < b; ++b2) dup |= (ss[b2] == sb);
        if (dup) return;                              // representative writes instead

        const int c4 = (bid % 15) * 128 + tid;        // float4 index 0..1919
        const float4* src = (const float4*)(W_in + (size_t)sb * CAPA * NN) + c4;
        float ax = 0.f, ay = 0.f, az = 0.f, aw = 0.f;
        #pragma unroll 1
        for (int g = 0; g < 3; ++g){                  // 10 loads in flight per group
            float4 w[10];
            #pragma unroll
            for (int uu = 0; uu < 10; ++uu)
                w[uu] = __ldg(src + (size_t)(g * 10 + uu) * NN4);
            #pragma unroll
            for (int uu = 0; uu < 10; ++uu){          // integer counts: exact any order
                ax += w[uu].x; ay += w[uu].y; az += w[uu].z; aw += w[uu].w;
            }
        }
        uchar4 r;
        r.x = (unsigned char)(int)ax; r.y = (unsigned char)(int)ay;
        r.z = (unsigned char)(int)az; r.w = (unsigned char)(int)aw;
        ((uchar4*)g_scores8[b])[c4] = r;
    } else {
        // ---- colnorm + rowbits for destination assembly a ------------------
        __shared__ int      sp2[NASM];
        __shared__ int      qlist[NASM];
        __shared__ unsigned rbl[QCH * CAPA];
        __shared__ int      cnt[CAPA];
        __shared__ int      snq;
        const int a = bid - S1BLK;
        sp2[tid]       = p[tid];
        sp2[tid + 128] = p[tid + 128];
        if (tid < CAPA) cnt[tid] = 0;
        __syncthreads();
        if (tid < 32){                                // warp 0: sources pointing to a
            int run = 0;
            for (int g = 0; g < 8; ++g){
                bool m = (sp2[g * 32 + tid] == a);
                unsigned bal = __ballot_sync(0xffffffffu, m);
                if (m) qlist[run + __popc(bal & ((1u << tid) - 1u))] = g * 32 + tid;
                run += __popc(bal);
            }
            if (tid == 0) snq = run;
        }
        __syncthreads();
        const int nq = snq;
        for (int c0 = 0; c0 < nq; c0 += QCH){
            const int nqc   = min(QCH, nq - c0);
            const int tasks = nqc * CAPA;
            // pass 1: thread per (source,row) — contiguous 30-float read -> bits
            for (int i = tid; i < tasks; i += 128){
                int qi = i / CAPA, m = i % CAPA;
                int q  = qlist[c0 + qi];
                const float* row = W_rec + (size_t)(q * CAPA + m) * NN + a * CAPA;
                unsigned bits = 0;
                #pragma unroll
                for (int c = 0; c < CAPA; ++c)
                    if (row[c] != 0.f) bits |= (1u << c);
                rbl[i] = bits;
                g_rowbits[q * CAPA + m] = bits;       // unique owner, plain store
            }
            __syncthreads();
            // pass 2: counts from bits (thread c owns cnt[c])
            if (tid < CAPA){
                int add = 0;
                for (int w = 0; w < tasks; ++w) add += (rbl[w] >> tid) & 1;
                cnt[tid] += add;
            }
            __syncthreads();
        }
        if (tid < CAPA) g_invc[a * CAPA + tid] = 1.0f / fmaxf((float)cnt[tid], 1e-6f);
    }
}

// ---------------------------------------------------------------------------
// Main: one block per sample; 512 threads; hot arrays in dynamic shared.
// ---------------------------------------------------------------------------
__global__ void __launch_bounds__(NTM) pointer_ac_kernel(
    const int* __restrict__ p, const int* __restrict__ s,
    const int* __restrict__ k, float* __restrict__ out)
{
    extern __shared__ char dyn[];
    unsigned long long* cand = (unsigned long long*)dyn;      // [MAXC], chase phase
    unsigned char*      sc8  = (unsigned char*)dyn;           // [NN], kWTA phase (union)
    float*              sinvc = (float*)(dyn + 7680);         // [NN]
    unsigned int*       srb   = (unsigned int*)(dyn + 38400); // [NN]

    __shared__ int   warpHist[NWARP * 31];
    __shared__ int   hist[31];
    __shared__ int   sp[NASM];
    __shared__ int   ssamp[BATCH];
    __shared__ int   scnt[NASM];
    __shared__ int   sel[CAPA];
    __shared__ int   tgtl[CAPA];
    __shared__ unsigned int smask[CAPA];
    __shared__ unsigned int arb[CAPA];
    __shared__ int   warpSum[NWARP], warpOff[NWARP];
    __shared__ int   sT, sNG, sticket, sncand, sntgt, sbesta;

    const int b    = blockIdx.x;
    const int tid  = threadIdx.x;
    const int lane = tid & 31;
    const int wid  = tid >> 5;

    if (tid < NASM) sp[tid] = p[tid];
    if (tid < BATCH) ssamp[tid] = s[tid];
    const int kb = __ldg(&k[b]);
    if (tid < NWARP * 31) warpHist[tid] = 0;
    if (tid == 0) sticket = 0;

    #pragma unroll
    for (int r = 0; r < 4; ++r){                      // sinvc: 1920 float4
        int i = tid + r * NTM;
        if (i < NN4) ((float4*)sinvc)[i] = ((const float4*)g_invc)[i];
    }
    #pragma unroll
    for (int r = 0; r < 4; ++r){                      // srb: 1920 uint4
        int i = tid + r * NTM;
        if (i < NN4) ((uint4*)srb)[i] = ((const uint4*)g_rowbits)[i];
    }
    __syncthreads();

    // representative sample (first occurrence of s[b]) holds the scores
    int rep = b;
    for (int b2 = 0; b2 < BATCH; ++b2){
        if (ssamp[b2] == ssamp[b]){ rep = b2; break; }
    }
    if (tid < NN / 16)                                // sc8: 480 uint4 (byte array)
        ((uint4*)sc8)[tid] = ((const uint4*)g_scores8[rep])[tid];
    __syncthreads();

    // ====== dense kWTA via histogram (exact ints 0..30) =====================
    {
        int* myh = warpHist + wid * 31;
        const int base_j = tid * RPTM;                // contiguous segment
        #pragma unroll
        for (int i = 0; i < RPTM; ++i){
            int v = sc8[base_j + i];
            atomicAdd(&myh[v], 1);
        }
        __syncthreads();
        if (tid < 31){
            int c = 0;
            #pragma unroll
            for (int w = 0; w < NWARP; ++w) c += warpHist[w * 31 + tid];
            hist[tid] = c;
        }
        __syncthreads();
        if (tid == 0){
            int suf = 0, T = 0, ng = 0;
            for (int v = 30; v >= 0; --v){
                suf += hist[v];
                if (suf >= CAPA){ T = v; ng = suf - hist[v]; break; }
            }
            sT = T; sNG = ng;
        }
        __syncthreads();
        const int T    = sT;
        const int ng   = sNG;
        const int need = CAPA - ng;

        int cntT = 0;
        #pragma unroll
        for (int i = 0; i < RPTM; ++i) cntT += (sc8[base_j + i] == T);
        int incl = cntT;
        #pragma unroll
        for (int o = 1; o < 32; o <<= 1){
            int n = __shfl_up_sync(0xffffffffu, incl, o);
            if (lane >= o) incl += n;
        }
        if (lane == 31) warpSum[wid] = incl;
        __syncthreads();
        if (tid == 0){
            int run = 0;
            #pragma unroll
            for (int w = 0; w < NWARP; ++w){ warpOff[w] = run; run += warpSum[w]; }
        }
        __syncthreads();
        int slotT = warpOff[wid] + incl - cntT;

        #pragma unroll
        for (int i = 0; i < RPTM; ++i){
            int j = base_j + i;
            int v = sc8[j];
            if (v > T){
                int sl = atomicAdd(&sticket, 1);      // set order irrelevant
                sel[sl] = j;
            } else if (v == T){
                if (slotT < need) sel[ng + slotT] = j;
                ++slotT;
            }
        }
        __syncthreads();
    }

    // ====== recurrent pointer-chase: 3 light barriers per step ==============
    for (int t = 0; t < KMAX; ++t){
        if (t >= kb) break;                           // uniform per block

        // Phase A (warp 0): dedup targets, rowbits from shared
        if (wid == 0){
            int an = (lane < CAPA) ? sel[lane] : 0;
            int tg = (lane < CAPA) ? sp[an / CAPA] : (256 + lane);
            unsigned mm = __match_any_sync(0xffffffffu, tg);
            if (lane < CAPA) arb[lane] = srb[an];     // LDS only
            bool leader = (lane < CAPA) && ((int)(__ffs(mm) - 1) == lane);
            unsigned lb = __ballot_sync(0xffffffffu, leader);
            if (leader){
                int pos = __popc(lb & ((1u << lane) - 1u));
                tgtl[pos]  = tg;
                smask[pos] = mm;                      // source set for this target
            }
            if (lane == 0){ sntgt = __popc(lb); sncand = 0; }
        }
        __syncthreads();

        // Phase B: lane = column; warps stride over targets (<=30)
        const int ntg = sntgt;
        for (int idx = wid; idx < ntg; idx += NWARP){
            int a = tgtl[idx];
            unsigned srcs = smask[idx];
            int j = a * CAPA + lane;
            float ic = (lane < CAPA) ? sinvc[j] : 0.f;
            float vv = 0.f;
            while (srcs){                             // m ascending: same FP order
                int m = __ffs(srcs) - 1; srcs &= srcs - 1;
                if ((arb[m] >> lane) & 1u) vv += ic;  // lanes 30/31: bit always 0
            }
            bool pos = (lane < CAPA) && (vv > 0.f);
            unsigned bal = __ballot_sync(0xffffffffu, pos);
            if (bal){
                int ldr = __ffs(bal) - 1;
                int base = 0;
                if (lane == ldr) base = atomicAdd(&sncand, __popc(bal));
                base = __shfl_sync(0xffffffffu, base, ldr);
                if (pos) cand[base + __popc(bal & ((1u << lane) - 1u))] = make_key(vv, j);
            }
        }
        __syncthreads();

        // Phase C: rank-select top-30 (+ smallest-index zero fill)
        const int nc = sncand;
        for (int q = tid; q < nc; q += NTM){
            unsigned long long kq = cand[q];
            int rank = 0;
            for (int x = 0; x < nc; ++x) rank += (cand[x] > kq);
            if (rank < CAPA) sel[rank] = key_j(kq);
        }
        if (tid == 0 && nc < CAPA){
            int P = nc, j = 0;
            while (P < CAPA){
                bool ispos = false;
                for (int x = 0; x < nc; ++x) ispos |= (key_j(cand[x]) == j);
                if (!ispos) sel[P++] = j;
                ++j;
            }
        }
        __syncthreads();
    }

    // ====== overlaps -> argmax (warp 0 reduce) -> one-hot ===================
    if (tid < NASM) scnt[tid] = 0;
    __syncthreads();
    if (tid < CAPA) atomicAdd(&scnt[sel[tid] / CAPA], 1);
    __syncthreads();
    if (wid == 0){
        unsigned long long bk = 0;
        #pragma unroll
        for (int r = 0; r < NASM / 32; ++r){
            int a = lane + r * 32;
            unsigned long long key =
                (((unsigned long long)scnt[a]) << 32) | (unsigned)(NASM - 1 - a);
            if (key > bk) bk = key;                   // max count, then smallest a
        }
        #pragma unroll
        for (int o = 16; o > 0; o >>= 1){
            unsigned long long obk = __shfl_xor_sync(0xffffffffu, bk, o);
            if (obk > bk) bk = obk;
        }
        if (lane == 0) sbesta = NASM - 1 - (int)(bk & 0xffffffffull);
    }
    __syncthreads();
    if (tid < NASM) out[(size_t)b * NASM + tid] = (tid == sbesta) ? 1.0f : 0.0f;
}

// ---------------------------------------------------------------------------
extern "C" void kernel_launch(void* const* d_in, const int* in_sizes, int n_in,
                              void* d_out, int out_size)
{
    const int*   p     = (const int*)d_in[0];     // [256]
    const int*   s     = (const int*)d_in[1];     // [64]
    const int*   k     = (const int*)d_in[2];     // [64]
    const float* W_in  = (const float*)d_in[3];   // [7680*7680]
    const float* W_rec = (const float*)d_in[4];   // [7680*7680]
    float*       out   = (float*)d_out;           // [64*256]

    cudaFuncSetAttribute(pointer_ac_kernel,
                         cudaFuncAttributeMaxDynamicSharedMemorySize, SMEM_DYN_BYTES);
    prep_kernel<<<S1BLK + NASM, 128>>>(p, s, W_in, W_rec);
    pointer_ac_kernel<<<BATCH, NTM, SMEM_DYN_BYTES>>>(p, s, k, out);
}